// round 9
// baseline (speedup 1.0000x reference)
#include <cuda_runtime.h>
#include <cstdint>
#include <math.h>

#define D_MODEL 512
#define NHEAD   8
#define HD      64
#define WIN     32
#define BATCH   2
#define SEQ     2048

// Scratch (no cudaMalloc allowed)
__device__ float g_q[BATCH * NHEAD * SEQ * HD];
__device__ float g_k[BATCH * NHEAD * SEQ * HD];
__device__ float g_v[BATCH * NHEAD * SEQ * HD];
__device__ float g_attn[BATCH * SEQ * D_MODEL];

__device__ __forceinline__ float f2tf32(float f) {
    unsigned int u;
    asm("cvt.rna.tf32.f32 %0, %1;" : "=r"(u) : "f"(f));
    return __uint_as_float(u);
}

__device__ __forceinline__ void mma_tf32(float4& d,
    unsigned int a0, unsigned int a1, unsigned int a2, unsigned int a3,
    unsigned int b0, unsigned int b1)
{
    asm volatile(
        "mma.sync.aligned.m16n8k8.row.col.f32.tf32.tf32.f32 "
        "{%0,%1,%2,%3}, {%4,%5,%6,%7}, {%8,%9}, {%0,%1,%2,%3};\n"
        : "+f"(d.x), "+f"(d.y), "+f"(d.z), "+f"(d.w)
        : "r"(a0), "r"(a1), "r"(a2), "r"(a3), "r"(b0), "r"(b1));
}

// ---------------------------------------------------------------------------
// TF32 tensor-core GEMM, double-buffered, 512 threads = 16 warps (4m x 4n).
// BM=128, BK=32. Warp tile 32x(BN_/4). A smem row-major stride 36,
// B smem [k][n] stride BN_+8 — all fragment accesses conflict-free.
// 2 CTAs/SM -> 32 resident warps (occupancy-driven redesign).
// ---------------------------------------------------------------------------
#define BM 128
#define BK 32
#define AS_S 36

template<int BN_, bool SCATTER>
__global__ __launch_bounds__(512, 2) void mma_gemm(
    const float* __restrict__ A, const float* __restrict__ Bw,
    const float* __restrict__ bias, float* __restrict__ C,
    float* __restrict__ qo, float* __restrict__ ko, float* __restrict__ vo,
    int M, int N, int K)
{
    constexpr int WT_M = 32;
    constexpr int WT_N = BN_ / 4;                // 32 or 16
    constexpr int MF = WT_M / 16;                // 2
    constexpr int NF = WT_N / 8;                 // 4 or 2
    constexpr int BS_Sl = BN_ + 8;
    constexpr int BUF = BM * AS_S + BK * BS_Sl;
    constexpr int AF4 = (BM * BK) / 2048;        // 2
    constexpr int BF4 = (BK * BN_) / 2048;       // 2 or 1
    constexpr int BROW_F4 = BN_ / 4;

    extern __shared__ float smbuf[];

    const int tid  = threadIdx.x;
    const int bm   = blockIdx.y * BM;
    const int bn   = blockIdx.x * BN_;
    const int w    = tid >> 5;
    const int wm   = w & 3;            // 0..3
    const int wn   = w >> 2;           // 0..3
    const int lane = tid & 31;
    const int gid  = lane >> 2;
    const int tig  = lane & 3;

    float4 acc[MF][NF];
    #pragma unroll
    for (int i = 0; i < MF; i++)
        #pragma unroll
        for (int j = 0; j < NF; j++)
            acc[i][j] = make_float4(0.f, 0.f, 0.f, 0.f);

    float4 a_st[AF4], b_st[BF4];

    auto ldg_tiles = [&](int k0) {
        #pragma unroll
        for (int p = 0; p < AF4; p++) {
            const int idx = p * 512 + tid;
            const int r = idx >> 3, c = (idx & 7) << 2;
            a_st[p] = *(const float4*)&A[(size_t)(bm + r) * K + k0 + c];
        }
        #pragma unroll
        for (int p = 0; p < BF4; p++) {
            const int idx = p * 512 + tid;
            const int r = idx / BROW_F4, c = (idx % BROW_F4) << 2;
            b_st[p] = *(const float4*)&Bw[(size_t)(k0 + r) * N + bn + c];
        }
    };
    auto sts_tiles = [&](float* base) {
        float* As = base;
        float* Bs = base + BM * AS_S;
        #pragma unroll
        for (int p = 0; p < AF4; p++) {
            const int idx = p * 512 + tid;
            const int r = idx >> 3, c = (idx & 7) << 2;
            float4 t = a_st[p];
            t.x = f2tf32(t.x); t.y = f2tf32(t.y);
            t.z = f2tf32(t.z); t.w = f2tf32(t.w);
            *(float4*)&As[r * AS_S + c] = t;
        }
        #pragma unroll
        for (int p = 0; p < BF4; p++) {
            const int idx = p * 512 + tid;
            const int r = idx / BROW_F4, c = (idx % BROW_F4) << 2;
            float4 t = b_st[p];
            t.x = f2tf32(t.x); t.y = f2tf32(t.y);
            t.z = f2tf32(t.z); t.w = f2tf32(t.w);
            *(float4*)&Bs[r * BS_Sl + c] = t;
        }
    };
    auto compute = [&](const float* base) {
        const float* As = base;
        const float* Bs = base + BM * AS_S;
        #pragma unroll
        for (int ks = 0; ks < 4; ks++) {
            const int kk = ks * 8;
            unsigned int af[MF][4], bf[NF][2];
            #pragma unroll
            for (int mf = 0; mf < MF; mf++) {
                const int mb = wm * WT_M + mf * 16;
                af[mf][0] = __float_as_uint(As[(mb + gid)     * AS_S + kk + tig]);
                af[mf][1] = __float_as_uint(As[(mb + gid + 8) * AS_S + kk + tig]);
                af[mf][2] = __float_as_uint(As[(mb + gid)     * AS_S + kk + tig + 4]);
                af[mf][3] = __float_as_uint(As[(mb + gid + 8) * AS_S + kk + tig + 4]);
            }
            #pragma unroll
            for (int nf = 0; nf < NF; nf++) {
                const int nb = wn * WT_N + nf * 8;
                bf[nf][0] = __float_as_uint(Bs[(kk + tig)     * BS_Sl + nb + gid]);
                bf[nf][1] = __float_as_uint(Bs[(kk + tig + 4) * BS_Sl + nb + gid]);
            }
            #pragma unroll
            for (int mf = 0; mf < MF; mf++)
                #pragma unroll
                for (int nf = 0; nf < NF; nf++)
                    mma_tf32(acc[mf][nf],
                             af[mf][0], af[mf][1], af[mf][2], af[mf][3],
                             bf[nf][0], bf[nf][1]);
        }
    };

    const int NIT = K / BK;
    ldg_tiles(0);
    sts_tiles(smbuf);
    __syncthreads();
    int cur = 0;
    for (int it = 0; it < NIT; it++) {
        if (it + 1 < NIT) ldg_tiles((it + 1) * BK);
        compute(smbuf + cur * BUF);
        if (it + 1 < NIT) {
            sts_tiles(smbuf + (cur ^ 1) * BUF);
            __syncthreads();
            cur ^= 1;
        }
    }

    #pragma unroll
    for (int mf = 0; mf < MF; mf++) {
        #pragma unroll
        for (int nf = 0; nf < NF; nf++) {
            const int m0 = bm + wm * WT_M + mf * 16 + gid;
            const int n0 = bn + wn * WT_N + nf * 8 + tig * 2;
            const float bs0 = bias[n0], bs1 = bias[n0 + 1];
            float2 top = make_float2(acc[mf][nf].x + bs0, acc[mf][nf].y + bs1);
            float2 bot = make_float2(acc[mf][nf].z + bs0, acc[mf][nf].w + bs1);
            if (SCATTER) {
                const int t  = n0 >> 9;
                const int hh = (n0 >> 6) & 7;
                const int dd = n0 & 63;
                float* p = (t == 0) ? qo : (t == 1) ? ko : vo;
                {
                    const int bb = m0 >> 11, ss = m0 & 2047;
                    *(float2*)&p[((size_t)(bb * NHEAD + hh) * SEQ + ss) * HD + dd] = top;
                }
                {
                    const int m1 = m0 + 8;
                    const int bb = m1 >> 11, ss = m1 & 2047;
                    *(float2*)&p[((size_t)(bb * NHEAD + hh) * SEQ + ss) * HD + dd] = bot;
                }
            } else {
                *(float2*)&C[(size_t)m0 * N + n0]       = top;
                *(float2*)&C[(size_t)(m0 + 8) * N + n0] = bot;
            }
        }
    }
}

#define QKV_SMEM ((BM * AS_S + BK * (128 + 8)) * 2 * 4)   // 71680
#define OUT_SMEM ((BM * AS_S + BK * (64 + 8)) * 2 * 4)    // 55296

// ---------------------------------------------------------------------------
// Sliding-window attention, tf32 MMA (unchanged from R6).
// ---------------------------------------------------------------------------
#define TQ 64
#define TC 128
#define QS_S 68
#define KS_S 68
#define VS_S 72
#define P_S  132
#define KV_UNION (TC * VS_S)
#define ATTN_SMEM_FLOATS (TQ * QS_S + KV_UNION + TQ * P_S)
#define ATTN_SMEM_BYTES  (ATTN_SMEM_FLOATS * 4)

__global__ __launch_bounds__(256, 2) void window_attn_mma(
    const float* __restrict__ gq, const float* __restrict__ gk,
    const float* __restrict__ gv, float* __restrict__ out)
{
    const int s0  = blockIdx.x * TQ;
    const int h   = blockIdx.y;
    const int b   = blockIdx.z;
    const int tid = threadIdx.x;
    const size_t base = (size_t)(b * NHEAD + h) * SEQ;

    extern __shared__ float smem[];
    float* Qs = smem;
    float* KV = smem + TQ * QS_S;
    float* P  = KV + KV_UNION;

    const int d  = tid & 63;
    const int r0 = tid >> 6;
    const int w    = tid >> 5;
    const int lane = tid & 31;
    const int gid  = lane >> 2;
    const int tig  = lane & 3;
    const int wm   = w & 1;
    const int wn   = w >> 1;

    #pragma unroll
    for (int r = r0; r < TQ; r += 4)
        Qs[r * QS_S + d] = f2tf32(gq[(base + s0 + r) * HD + d] * 0.125f);
    #pragma unroll
    for (int c = r0; c < TC; c += 4) {
        const int idx = s0 - WIN + c;
        float val = 0.f;
        if (idx >= 0 && idx < SEQ) val = gk[(base + idx) * HD + d];
        KV[c * KS_S + d] = f2tf32(val);
    }
    __syncthreads();

    // GEMM1: S = Q @ K^T
    {
        float4 acc[2][4];
        #pragma unroll
        for (int i = 0; i < 2; i++)
            #pragma unroll
            for (int j = 0; j < 4; j++)
                acc[i][j] = make_float4(0.f, 0.f, 0.f, 0.f);

        #pragma unroll
        for (int ks = 0; ks < 8; ks++) {
            const int kk = ks * 8;
            unsigned int af[2][4], bf[4][2];
            #pragma unroll
            for (int mf = 0; mf < 2; mf++) {
                const int mb = wm * 32 + mf * 16;
                af[mf][0] = __float_as_uint(Qs[(mb + gid)     * QS_S + kk + tig]);
                af[mf][1] = __float_as_uint(Qs[(mb + gid + 8) * QS_S + kk + tig]);
                af[mf][2] = __float_as_uint(Qs[(mb + gid)     * QS_S + kk + tig + 4]);
                af[mf][3] = __float_as_uint(Qs[(mb + gid + 8) * QS_S + kk + tig + 4]);
            }
            #pragma unroll
            for (int nf = 0; nf < 4; nf++) {
                const int nb = wn * 32 + nf * 8;
                bf[nf][0] = __float_as_uint(KV[(nb + gid) * KS_S + kk + tig]);
                bf[nf][1] = __float_as_uint(KV[(nb + gid) * KS_S + kk + tig + 4]);
            }
            #pragma unroll
            for (int mf = 0; mf < 2; mf++)
                #pragma unroll
                for (int nf = 0; nf < 4; nf++)
                    mma_tf32(acc[mf][nf],
                             af[mf][0], af[mf][1], af[mf][2], af[mf][3],
                             bf[nf][0], bf[nf][1]);
        }
        #pragma unroll
        for (int mf = 0; mf < 2; mf++) {
            #pragma unroll
            for (int nf = 0; nf < 4; nf++) {
                const int m0 = wm * 32 + mf * 16 + gid;
                const int n0 = wn * 32 + nf * 8 + tig * 2;
                *(float2*)&P[m0 * P_S + n0]       = make_float2(acc[mf][nf].x, acc[mf][nf].y);
                *(float2*)&P[(m0 + 8) * P_S + n0] = make_float2(acc[mf][nf].z, acc[mf][nf].w);
            }
        }
    }
    __syncthreads();

    #pragma unroll
    for (int c = r0; c < TC; c += 4) {
        const int idx = s0 - WIN + c;
        float val = 0.f;
        if (idx >= 0 && idx < SEQ) val = gv[(base + idx) * HD + d];
        KV[c * VS_S + d] = f2tf32(val);
    }

    // Masked softmax
    {
        for (int q = w; q < TQ; q += 8) {
            float vals[4];
            #pragma unroll
            for (int k = 0; k < 4; k++) {
                const int c = lane + k * 32;
                const int idx = s0 - WIN + c;
                const bool valid = (c >= q) && (c <= q + 2 * WIN) && (idx >= 0) && (idx < SEQ);
                vals[k] = valid ? P[q * P_S + c] : -1e30f;
            }
            float m = fmaxf(fmaxf(vals[0], vals[1]), fmaxf(vals[2], vals[3]));
            #pragma unroll
            for (int off = 16; off > 0; off >>= 1)
                m = fmaxf(m, __shfl_xor_sync(0xffffffffu, m, off));
            float e[4], sum = 0.f;
            #pragma unroll
            for (int k = 0; k < 4; k++) { e[k] = __expf(vals[k] - m); sum += e[k]; }
            #pragma unroll
            for (int off = 16; off > 0; off >>= 1)
                sum += __shfl_xor_sync(0xffffffffu, sum, off);
            const float inv = 1.0f / sum;
            #pragma unroll
            for (int k = 0; k < 4; k++)
                P[q * P_S + lane + k * 32] = f2tf32(e[k] * inv);
        }
    }
    __syncthreads();

    // GEMM2: O = P @ V
    {
        float4 acc[2][2];
        #pragma unroll
        for (int i = 0; i < 2; i++)
            #pragma unroll
            for (int j = 0; j < 2; j++)
                acc[i][j] = make_float4(0.f, 0.f, 0.f, 0.f);

        #pragma unroll 4
        for (int ks = 0; ks < 16; ks++) {
            const int kk = ks * 8;
            unsigned int af[2][4], bf[2][2];
            #pragma unroll
            for (int mf = 0; mf < 2; mf++) {
                const int mb = wm * 32 + mf * 16;
                af[mf][0] = __float_as_uint(P[(mb + gid)     * P_S + kk + tig]);
                af[mf][1] = __float_as_uint(P[(mb + gid + 8) * P_S + kk + tig]);
                af[mf][2] = __float_as_uint(P[(mb + gid)     * P_S + kk + tig + 4]);
                af[mf][3] = __float_as_uint(P[(mb + gid + 8) * P_S + kk + tig + 4]);
            }
            #pragma unroll
            for (int nf = 0; nf < 2; nf++) {
                const int nb = wn * 16 + nf * 8;
                bf[nf][0] = __float_as_uint(KV[(kk + tig)     * VS_S + nb + gid]);
                bf[nf][1] = __float_as_uint(KV[(kk + tig + 4) * VS_S + nb + gid]);
            }
            #pragma unroll
            for (int mf = 0; mf < 2; mf++)
                #pragma unroll
                for (int nf = 0; nf < 2; nf++)
                    mma_tf32(acc[mf][nf],
                             af[mf][0], af[mf][1], af[mf][2], af[mf][3],
                             bf[nf][0], bf[nf][1]);
        }
        #pragma unroll
        for (int mf = 0; mf < 2; mf++) {
            #pragma unroll
            for (int nf = 0; nf < 2; nf++) {
                const int m0 = wm * 32 + mf * 16 + gid;
                const int n0 = wn * 16 + nf * 8 + tig * 2;
                size_t o0 = ((size_t)b * SEQ + s0 + m0) * D_MODEL + h * HD + n0;
                *(float2*)&out[o0] = make_float2(acc[mf][nf].x, acc[mf][nf].y);
                size_t o1 = ((size_t)b * SEQ + s0 + m0 + 8) * D_MODEL + h * HD + n0;
                *(float2*)&out[o1] = make_float2(acc[mf][nf].z, acc[mf][nf].w);
            }
        }
    }
}

// ---------------------------------------------------------------------------
extern "C" void kernel_launch(void* const* d_in, const int* in_sizes, int n_in,
                              void* d_out, int out_size)
{
    const float* x     = (const float*)d_in[0];
    const float* w_qkv = (const float*)d_in[1];
    const float* b_qkv = (const float*)d_in[2];
    const float* w_out = (const float*)d_in[3];
    const float* b_out = (const float*)d_in[4];
    float* out = (float*)d_out;

    float *q, *k, *v, *attn;
    cudaGetSymbolAddress((void**)&q,    g_q);
    cudaGetSymbolAddress((void**)&k,    g_k);
    cudaGetSymbolAddress((void**)&v,    g_v);
    cudaGetSymbolAddress((void**)&attn, g_attn);

    const int M = BATCH * SEQ;     // 4096
    const int K = D_MODEL;         // 512

    cudaFuncSetAttribute((const void*)mma_gemm<128, true>,
                         cudaFuncAttributeMaxDynamicSharedMemorySize, QKV_SMEM);
    cudaFuncSetAttribute((const void*)mma_gemm<64, false>,
                         cudaFuncAttributeMaxDynamicSharedMemorySize, OUT_SMEM);
    cudaFuncSetAttribute(window_attn_mma,
                         cudaFuncAttributeMaxDynamicSharedMemorySize, ATTN_SMEM_BYTES);

    // 1) QKV projection (tf32 MMA, 512 threads, 16 warps) + head-major scatter
    {
        dim3 grid((3 * D_MODEL) / 128, M / BM);   // 12 x 32 = 384 CTAs
        mma_gemm<128, true><<<grid, 512, QKV_SMEM>>>(
            x, w_qkv, b_qkv, nullptr, q, k, v, M, 3 * D_MODEL, K);
    }
    // 2) Windowed attention (tf32 MMA)
    {
        dim3 grid(SEQ / TQ, NHEAD, BATCH);        // 512 CTAs
        window_attn_mma<<<grid, 256, ATTN_SMEM_BYTES>>>(q, k, v, attn);
    }
    // 3) Output projection (tf32 MMA, 512 threads)
    {
        dim3 grid(D_MODEL / 64, M / BM);          // 256 CTAs
        mma_gemm<64, false><<<grid, 512, OUT_SMEM>>>(
            attn, w_out, b_out, out, nullptr, nullptr, nullptr,
            M, D_MODEL, K);
    }
}

// round 10
// speedup vs baseline: 1.2141x; 1.2141x over previous
#include <cuda_runtime.h>
#include <cstdint>
#include <math.h>

#define D_MODEL 512
#define NHEAD   8
#define HD      64
#define WIN     32
#define BATCH   2
#define SEQ     2048

// Scratch (no cudaMalloc allowed)
__device__ float g_q[BATCH * NHEAD * SEQ * HD];
__device__ float g_k[BATCH * NHEAD * SEQ * HD];
__device__ float g_v[BATCH * NHEAD * SEQ * HD];
__device__ float g_attn[BATCH * SEQ * D_MODEL];

__device__ __forceinline__ float f2tf32(float f) {
    unsigned int u;
    asm("cvt.rna.tf32.f32 %0, %1;" : "=r"(u) : "f"(f));
    return __uint_as_float(u);
}

__device__ __forceinline__ void mma_tf32(float4& d,
    unsigned int a0, unsigned int a1, unsigned int a2, unsigned int a3,
    unsigned int b0, unsigned int b1)
{
    asm volatile(
        "mma.sync.aligned.m16n8k8.row.col.f32.tf32.tf32.f32 "
        "{%0,%1,%2,%3}, {%4,%5,%6,%7}, {%8,%9}, {%0,%1,%2,%3};\n"
        : "+f"(d.x), "+f"(d.y), "+f"(d.z), "+f"(d.w)
        : "r"(a0), "r"(a1), "r"(a2), "r"(a3), "r"(b0), "r"(b1));
}

__device__ __forceinline__ unsigned smem_u32(const void* p) {
    return (unsigned)__cvta_generic_to_shared(p);
}

// ldmatrix x4: four 8x4-tf32 tiles -> a0,a1,a2,a3 of m16k8 fragment.
__device__ __forceinline__ void ldsm_x4(unsigned int* r, unsigned addr) {
    asm volatile("ldmatrix.sync.aligned.m8n8.x4.shared.b16 {%0,%1,%2,%3}, [%4];"
        : "=r"(r[0]), "=r"(r[1]), "=r"(r[2]), "=r"(r[3]) : "r"(addr));
}
// ldmatrix x2: two 8x4-tf32 tiles -> b0,b1 of n8k8 fragment.
__device__ __forceinline__ void ldsm_x2(unsigned int* r, unsigned addr) {
    asm volatile("ldmatrix.sync.aligned.m8n8.x2.shared.b16 {%0,%1}, [%2];"
        : "=r"(r[0]), "=r"(r[1]) : "r"(addr));
}

// ---------------------------------------------------------------------------
// TF32 tensor-core GEMM, double-buffered (R6 config), A-frags via ldmatrix.
// BM=128, BK=32, 256 threads = 8 warps. BN=128: 2x4 warps, tile 64x32.
// BN=64: 4x2 warps, tile 32x32. A stride 36 (144B == 16 mod 128 -> LDSM
// phases conflict-free). B [k][n] stride BN+8, scalar LDS (conflict-free).
// ---------------------------------------------------------------------------
#define BM 128
#define BK 32
#define AS_S 36

template<int BN_, bool SCATTER>
__global__ __launch_bounds__(256, 2) void mma_gemm(
    const float* __restrict__ A, const float* __restrict__ Bw,
    const float* __restrict__ bias, float* __restrict__ C,
    float* __restrict__ qo, float* __restrict__ ko, float* __restrict__ vo,
    int M, int N, int K)
{
    constexpr int WM_WARPS = (BN_ == 128) ? 2 : 4;
    constexpr int WN_WARPS = 8 / WM_WARPS;
    constexpr int WT_M = BM / WM_WARPS;          // 64 or 32
    constexpr int WT_N = BN_ / WN_WARPS;         // 32
    constexpr int MF = WT_M / 16;                // 4 or 2
    constexpr int NF = WT_N / 8;                 // 4
    constexpr int BS_Sl = BN_ + 8;
    constexpr int BUF = BM * AS_S + BK * BS_Sl;
    constexpr int BF4 = (BK * BN_) / 1024;
    constexpr int BROW_F4 = BN_ / 4;

    extern __shared__ float smbuf[];

    const int tid  = threadIdx.x;
    const int bm   = blockIdx.y * BM;
    const int bn   = blockIdx.x * BN_;
    const int w    = tid >> 5;
    const int wm   = w % WM_WARPS;
    const int wn   = w / WM_WARPS;
    const int lane = tid & 31;
    const int gid  = lane >> 2;
    const int tig  = lane & 3;
    // ldmatrix per-lane source row/col for x4 (a0..a3)
    const int lm_mat  = lane >> 3;
    const int lm_row  = lane & 7;
    const int a_roff  = (lm_mat & 1) * 8 + lm_row;
    const int a_koff  = (lm_mat >> 1) * 4;

    float4 acc[MF][NF];
    #pragma unroll
    for (int i = 0; i < MF; i++)
        #pragma unroll
        for (int j = 0; j < NF; j++)
            acc[i][j] = make_float4(0.f, 0.f, 0.f, 0.f);

    float4 a_st[4], b_st[BF4];

    auto ldg_tiles = [&](int k0) {
        #pragma unroll
        for (int p = 0; p < 4; p++) {
            const int idx = p * 256 + tid;
            const int r = idx >> 3, c = (idx & 7) << 2;
            a_st[p] = *(const float4*)&A[(size_t)(bm + r) * K + k0 + c];
        }
        #pragma unroll
        for (int p = 0; p < BF4; p++) {
            const int idx = p * 256 + tid;
            const int r = idx / BROW_F4, c = (idx % BROW_F4) << 2;
            b_st[p] = *(const float4*)&Bw[(size_t)(k0 + r) * N + bn + c];
        }
    };
    auto sts_tiles = [&](float* base) {
        float* As = base;
        float* Bs = base + BM * AS_S;
        #pragma unroll
        for (int p = 0; p < 4; p++) {
            const int idx = p * 256 + tid;
            const int r = idx >> 3, c = (idx & 7) << 2;
            float4 t = a_st[p];
            t.x = f2tf32(t.x); t.y = f2tf32(t.y);
            t.z = f2tf32(t.z); t.w = f2tf32(t.w);
            *(float4*)&As[r * AS_S + c] = t;
        }
        #pragma unroll
        for (int p = 0; p < BF4; p++) {
            const int idx = p * 256 + tid;
            const int r = idx / BROW_F4, c = (idx % BROW_F4) << 2;
            float4 t = b_st[p];
            t.x = f2tf32(t.x); t.y = f2tf32(t.y);
            t.z = f2tf32(t.z); t.w = f2tf32(t.w);
            *(float4*)&Bs[r * BS_Sl + c] = t;
        }
    };
    auto compute = [&](const float* base) {
        const float* As = base;
        const float* Bs = base + BM * AS_S;
        const unsigned a_base = smem_u32(
            &As[(wm * WT_M + a_roff) * AS_S + a_koff]);
        #pragma unroll
        for (int ks = 0; ks < 4; ks++) {
            const int kk = ks * 8;
            unsigned int af[MF][4], bf[NF][2];
            #pragma unroll
            for (int mf = 0; mf < MF; mf++)
                ldsm_x4(af[mf], a_base + (mf * 16 * AS_S + kk) * 4);
            #pragma unroll
            for (int nf = 0; nf < NF; nf++) {
                const int nb = wn * WT_N + nf * 8;
                bf[nf][0] = __float_as_uint(Bs[(kk + tig)     * BS_Sl + nb + gid]);
                bf[nf][1] = __float_as_uint(Bs[(kk + tig + 4) * BS_Sl + nb + gid]);
            }
            #pragma unroll
            for (int mf = 0; mf < MF; mf++)
                #pragma unroll
                for (int nf = 0; nf < NF; nf++)
                    mma_tf32(acc[mf][nf],
                             af[mf][0], af[mf][1], af[mf][2], af[mf][3],
                             bf[nf][0], bf[nf][1]);
        }
    };

    const int NIT = K / BK;
    ldg_tiles(0);
    sts_tiles(smbuf);
    __syncthreads();
    int cur = 0;
    for (int it = 0; it < NIT; it++) {
        if (it + 1 < NIT) ldg_tiles((it + 1) * BK);
        compute(smbuf + cur * BUF);
        if (it + 1 < NIT) {
            sts_tiles(smbuf + (cur ^ 1) * BUF);
            __syncthreads();
            cur ^= 1;
        }
    }

    #pragma unroll
    for (int mf = 0; mf < MF; mf++) {
        #pragma unroll
        for (int nf = 0; nf < NF; nf++) {
            const int m0 = bm + wm * WT_M + mf * 16 + gid;
            const int n0 = bn + wn * WT_N + nf * 8 + tig * 2;
            const float bs0 = bias[n0], bs1 = bias[n0 + 1];
            float2 top = make_float2(acc[mf][nf].x + bs0, acc[mf][nf].y + bs1);
            float2 bot = make_float2(acc[mf][nf].z + bs0, acc[mf][nf].w + bs1);
            if (SCATTER) {
                const int t  = n0 >> 9;
                const int hh = (n0 >> 6) & 7;
                const int dd = n0 & 63;
                float* p = (t == 0) ? qo : (t == 1) ? ko : vo;
                {
                    const int bb = m0 >> 11, ss = m0 & 2047;
                    *(float2*)&p[((size_t)(bb * NHEAD + hh) * SEQ + ss) * HD + dd] = top;
                }
                {
                    const int m1 = m0 + 8;
                    const int bb = m1 >> 11, ss = m1 & 2047;
                    *(float2*)&p[((size_t)(bb * NHEAD + hh) * SEQ + ss) * HD + dd] = bot;
                }
            } else {
                *(float2*)&C[(size_t)m0 * N + n0]       = top;
                *(float2*)&C[(size_t)(m0 + 8) * N + n0] = bot;
            }
        }
    }
}

#define QKV_SMEM ((BM * AS_S + BK * (128 + 8)) * 2 * 4)   // 71680
#define OUT_SMEM ((BM * AS_S + BK * (64 + 8)) * 2 * 4)    // 55296

// ---------------------------------------------------------------------------
// Sliding-window attention, tf32 MMA + ldmatrix.
// GEMM1: A=Q (ldsm x4), B=K stored [n][k] (ldsm x2) — both conflict-free
// (strides 68 floats = 272B == 16 mod 128).
// GEMM2: A=P (ldsm x4, stride 132 = 528B == 16 mod 128), B=V scalar LDS.
// ---------------------------------------------------------------------------
#define TQ 64
#define TC 128
#define QS_S 68
#define KS_S 68
#define VS_S 72
#define P_S  132
#define KV_UNION (TC * VS_S)
#define ATTN_SMEM_FLOATS (TQ * QS_S + KV_UNION + TQ * P_S)
#define ATTN_SMEM_BYTES  (ATTN_SMEM_FLOATS * 4)

__global__ __launch_bounds__(256, 2) void window_attn_mma(
    const float* __restrict__ gq, const float* __restrict__ gk,
    const float* __restrict__ gv, float* __restrict__ out)
{
    const int s0  = blockIdx.x * TQ;
    const int h   = blockIdx.y;
    const int b   = blockIdx.z;
    const int tid = threadIdx.x;
    const size_t base = (size_t)(b * NHEAD + h) * SEQ;

    extern __shared__ float smem[];
    float* Qs = smem;
    float* KV = smem + TQ * QS_S;
    float* P  = KV + KV_UNION;

    const int d  = tid & 63;
    const int r0 = tid >> 6;
    const int w    = tid >> 5;
    const int lane = tid & 31;
    const int gid  = lane >> 2;
    const int tig  = lane & 3;
    const int wm   = w & 1;
    const int wn   = w >> 1;
    // ldmatrix lane mappings
    const int lm_mat = lane >> 3;
    const int lm_row = lane & 7;
    const int a_roff = (lm_mat & 1) * 8 + lm_row;
    const int a_koff = (lm_mat >> 1) * 4;
    const int l2     = lane & 15;            // x2 uses lanes 0-15
    const int b_row  = l2 & 7;
    const int b_koff = (l2 >> 3) * 4;

    #pragma unroll
    for (int r = r0; r < TQ; r += 4)
        Qs[r * QS_S + d] = f2tf32(gq[(base + s0 + r) * HD + d] * 0.125f);
    #pragma unroll
    for (int c = r0; c < TC; c += 4) {
        const int idx = s0 - WIN + c;
        float val = 0.f;
        if (idx >= 0 && idx < SEQ) val = gk[(base + idx) * HD + d];
        KV[c * KS_S + d] = f2tf32(val);
    }
    __syncthreads();

    // GEMM1: S = Q @ K^T (A ldsm x4, B ldsm x2)
    {
        float4 acc[2][4];
        #pragma unroll
        for (int i = 0; i < 2; i++)
            #pragma unroll
            for (int j = 0; j < 4; j++)
                acc[i][j] = make_float4(0.f, 0.f, 0.f, 0.f);

        const unsigned a_base = smem_u32(&Qs[(wm * 32 + a_roff) * QS_S + a_koff]);
        const unsigned b_base = smem_u32(&KV[(wn * 32 + b_row) * KS_S + b_koff]);

        #pragma unroll
        for (int ks = 0; ks < 8; ks++) {
            const int kk = ks * 8;
            unsigned int af[2][4], bf[4][2];
            #pragma unroll
            for (int mf = 0; mf < 2; mf++)
                ldsm_x4(af[mf], a_base + (mf * 16 * QS_S + kk) * 4);
            #pragma unroll
            for (int nf = 0; nf < 4; nf++)
                ldsm_x2(bf[nf], b_base + (nf * 8 * KS_S + kk) * 4);
            #pragma unroll
            for (int mf = 0; mf < 2; mf++)
                #pragma unroll
                for (int nf = 0; nf < 4; nf++)
                    mma_tf32(acc[mf][nf],
                             af[mf][0], af[mf][1], af[mf][2], af[mf][3],
                             bf[nf][0], bf[nf][1]);
        }
        #pragma unroll
        for (int mf = 0; mf < 2; mf++) {
            #pragma unroll
            for (int nf = 0; nf < 4; nf++) {
                const int m0 = wm * 32 + mf * 16 + gid;
                const int n0 = wn * 32 + nf * 8 + tig * 2;
                *(float2*)&P[m0 * P_S + n0]       = make_float2(acc[mf][nf].x, acc[mf][nf].y);
                *(float2*)&P[(m0 + 8) * P_S + n0] = make_float2(acc[mf][nf].z, acc[mf][nf].w);
            }
        }
    }
    __syncthreads();

    #pragma unroll
    for (int c = r0; c < TC; c += 4) {
        const int idx = s0 - WIN + c;
        float val = 0.f;
        if (idx >= 0 && idx < SEQ) val = gv[(base + idx) * HD + d];
        KV[c * VS_S + d] = f2tf32(val);
    }

    // Masked softmax
    {
        for (int q = w; q < TQ; q += 8) {
            float vals[4];
            #pragma unroll
            for (int k = 0; k < 4; k++) {
                const int c = lane + k * 32;
                const int idx = s0 - WIN + c;
                const bool valid = (c >= q) && (c <= q + 2 * WIN) && (idx >= 0) && (idx < SEQ);
                vals[k] = valid ? P[q * P_S + c] : -1e30f;
            }
            float m = fmaxf(fmaxf(vals[0], vals[1]), fmaxf(vals[2], vals[3]));
            #pragma unroll
            for (int off = 16; off > 0; off >>= 1)
                m = fmaxf(m, __shfl_xor_sync(0xffffffffu, m, off));
            float e[4], sum = 0.f;
            #pragma unroll
            for (int k = 0; k < 4; k++) { e[k] = __expf(vals[k] - m); sum += e[k]; }
            #pragma unroll
            for (int off = 16; off > 0; off >>= 1)
                sum += __shfl_xor_sync(0xffffffffu, sum, off);
            const float inv = 1.0f / sum;
            #pragma unroll
            for (int k = 0; k < 4; k++)
                P[q * P_S + lane + k * 32] = f2tf32(e[k] * inv);
        }
    }
    __syncthreads();

    // GEMM2: O = P @ V (A ldsm x4, B scalar)
    {
        float4 acc[2][2];
        #pragma unroll
        for (int i = 0; i < 2; i++)
            #pragma unroll
            for (int j = 0; j < 2; j++)
                acc[i][j] = make_float4(0.f, 0.f, 0.f, 0.f);

        const unsigned p_base = smem_u32(&P[(wm * 32 + a_roff) * P_S + a_koff]);

        #pragma unroll 4
        for (int ks = 0; ks < 16; ks++) {
            const int kk = ks * 8;
            unsigned int af[2][4], bf[2][2];
            #pragma unroll
            for (int mf = 0; mf < 2; mf++)
                ldsm_x4(af[mf], p_base + (mf * 16 * P_S + kk) * 4);
            #pragma unroll
            for (int nf = 0; nf < 2; nf++) {
                const int nb = wn * 16 + nf * 8;
                bf[nf][0] = __float_as_uint(KV[(kk + tig)     * VS_S + nb + gid]);
                bf[nf][1] = __float_as_uint(KV[(kk + tig + 4) * VS_S + nb + gid]);
            }
            #pragma unroll
            for (int mf = 0; mf < 2; mf++)
                #pragma unroll
                for (int nf = 0; nf < 2; nf++)
                    mma_tf32(acc[mf][nf],
                             af[mf][0], af[mf][1], af[mf][2], af[mf][3],
                             bf[nf][0], bf[nf][1]);
        }
        #pragma unroll
        for (int mf = 0; mf < 2; mf++) {
            #pragma unroll
            for (int nf = 0; nf < 2; nf++) {
                const int m0 = wm * 32 + mf * 16 + gid;
                const int n0 = wn * 16 + nf * 8 + tig * 2;
                size_t o0 = ((size_t)b * SEQ + s0 + m0) * D_MODEL + h * HD + n0;
                *(float2*)&out[o0] = make_float2(acc[mf][nf].x, acc[mf][nf].y);
                size_t o1 = ((size_t)b * SEQ + s0 + m0 + 8) * D_MODEL + h * HD + n0;
                *(float2*)&out[o1] = make_float2(acc[mf][nf].z, acc[mf][nf].w);
            }
        }
    }
}

// ---------------------------------------------------------------------------
extern "C" void kernel_launch(void* const* d_in, const int* in_sizes, int n_in,
                              void* d_out, int out_size)
{
    const float* x     = (const float*)d_in[0];
    const float* w_qkv = (const float*)d_in[1];
    const float* b_qkv = (const float*)d_in[2];
    const float* w_out = (const float*)d_in[3];
    const float* b_out = (const float*)d_in[4];
    float* out = (float*)d_out;

    float *q, *k, *v, *attn;
    cudaGetSymbolAddress((void**)&q,    g_q);
    cudaGetSymbolAddress((void**)&k,    g_k);
    cudaGetSymbolAddress((void**)&v,    g_v);
    cudaGetSymbolAddress((void**)&attn, g_attn);

    const int M = BATCH * SEQ;     // 4096
    const int K = D_MODEL;         // 512

    cudaFuncSetAttribute((const void*)mma_gemm<128, true>,
                         cudaFuncAttributeMaxDynamicSharedMemorySize, QKV_SMEM);
    cudaFuncSetAttribute((const void*)mma_gemm<64, false>,
                         cudaFuncAttributeMaxDynamicSharedMemorySize, OUT_SMEM);
    cudaFuncSetAttribute(window_attn_mma,
                         cudaFuncAttributeMaxDynamicSharedMemorySize, ATTN_SMEM_BYTES);

    // 1) QKV projection (tf32 MMA + ldmatrix) with head-major scatter
    {
        dim3 grid((3 * D_MODEL) / 128, M / BM);   // 12 x 32 = 384 CTAs
        mma_gemm<128, true><<<grid, 256, QKV_SMEM>>>(
            x, w_qkv, b_qkv, nullptr, q, k, v, M, 3 * D_MODEL, K);
    }
    // 2) Windowed attention (tf32 MMA + ldmatrix)
    {
        dim3 grid(SEQ / TQ, NHEAD, BATCH);        // 512 CTAs
        window_attn_mma<<<grid, 256, ATTN_SMEM_BYTES>>>(q, k, v, attn);
    }
    // 3) Output projection (tf32 MMA + ldmatrix)
    {
        dim3 grid(D_MODEL / 64, M / BM);          // 256 CTAs
        mma_gemm<64, false><<<grid, 256, OUT_SMEM>>>(
            attn, w_out, b_out, out, nullptr, nullptr, nullptr,
            M, D_MODEL, K);
    }
}

// round 13
// speedup vs baseline: 1.5153x; 1.2481x over previous
#include <cuda_runtime.h>
#include <cuda_fp16.h>
#include <cstdint>
#include <math.h>

#define D_MODEL 512
#define NHEAD   8
#define HD      64
#define WIN     32
#define BATCH   2
#define SEQ     2048
#define MTOT    (BATCH * SEQ)          // 4096
#define NQKV    (3 * D_MODEL)          // 1536

// Scratch (no cudaMalloc allowed)
__device__ float  g_qkv[MTOT * NQKV];            // [m][1536]
__device__ __half g_wqkv_t[NQKV * D_MODEL];      // w_qkv^T [n][k] half
__device__ __half g_wout_t[D_MODEL * D_MODEL];   // w_out^T [n][k] half
__device__ float  g_attn[MTOT * D_MODEL];

__device__ __forceinline__ unsigned smem_u32(const void* p) {
    return (unsigned)__cvta_generic_to_shared(p);
}
__device__ __forceinline__ void ldsm_x4(unsigned int* r, unsigned addr) {
    asm volatile("ldmatrix.sync.aligned.m8n8.x4.shared.b16 {%0,%1,%2,%3}, [%4];"
        : "=r"(r[0]), "=r"(r[1]), "=r"(r[2]), "=r"(r[3]) : "r"(addr));
}
__device__ __forceinline__ void ldsm_x2(unsigned int* r, unsigned addr) {
    asm volatile("ldmatrix.sync.aligned.m8n8.x2.shared.b16 {%0,%1}, [%2];"
        : "=r"(r[0]), "=r"(r[1]) : "r"(addr));
}
__device__ __forceinline__ void mma_f16(float4& d,
    unsigned a0, unsigned a1, unsigned a2, unsigned a3,
    unsigned b0, unsigned b1)
{
    asm volatile(
        "mma.sync.aligned.m16n8k16.row.col.f32.f16.f16.f32 "
        "{%0,%1,%2,%3}, {%4,%5,%6,%7}, {%8,%9}, {%0,%1,%2,%3};\n"
        : "+f"(d.x), "+f"(d.y), "+f"(d.z), "+f"(d.w)
        : "r"(a0), "r"(a1), "r"(a2), "r"(a3), "r"(b0), "r"(b1));
}

// ---------------------------------------------------------------------------
// Weight transpose: w[k][n] f32 -> wt[n][k] half.  32x32 tiles.
// ---------------------------------------------------------------------------
__global__ __launch_bounds__(256) void transpose_wh(
    const float* __restrict__ w, __half* __restrict__ wt, int K, int N)
{
    __shared__ float t[32][33];
    const int bx = blockIdx.x * 32;   // n block
    const int by = blockIdx.y * 32;   // k block
    const int x = threadIdx.x & 31;
    const int y0 = threadIdx.x >> 5;
    #pragma unroll
    for (int j = 0; j < 32; j += 8)
        t[y0 + j][x] = w[(size_t)(by + y0 + j) * N + bx + x];
    __syncthreads();
    #pragma unroll
    for (int j = 0; j < 32; j += 8)
        wt[(size_t)(bx + y0 + j) * K + by + x] = __float2half_rn(t[x][y0 + j]);
}

// ---------------------------------------------------------------------------
// FP16 tensor-core GEMM, double-buffered: C[M,N] = A[M,K] @ Bt^T + bias
// A fp32 [m][k]; Bt half [n][k]. BM=128, BK=32 (2 k16-steps), 256 thr, 8 warps.
// A smem [128][40] half, B smem [BN][40] half — stride 80B: 16B-aligned rows,
// ldmatrix phase step 5 (conflict-free).
// ---------------------------------------------------------------------------
#define BM 128
#define BK 32
#define TS_H 40                                 // tile k-stride in halves

template<int BN_>
__global__ __launch_bounds__(256, 2) void gemm_f16(
    const float* __restrict__ A, const __half* __restrict__ Bt,
    const float* __restrict__ bias, float* __restrict__ C,
    int M, int N, int K)
{
    constexpr int WM_WARPS = (BN_ == 128) ? 2 : 4;
    constexpr int WT_M = BM / WM_WARPS;          // 64 or 32
    constexpr int WT_N = BN_ / (8 / WM_WARPS);   // 32
    constexpr int MF = WT_M / 16;                // 4 or 2
    constexpr int NF = WT_N / 8;                 // 4
    constexpr int BUFH = BM * TS_H + BN_ * TS_H; // halves per buffer
    constexpr int ASEG = 2;                      // 128*32/(256*8)
    constexpr int BSEG = (BN_ * BK) / 2048;      // 2 or 1

    extern __shared__ __half sh16[];

    const int tid  = threadIdx.x;
    const int bm   = blockIdx.y * BM;
    const int bn   = blockIdx.x * BN_;
    const int w    = tid >> 5;
    const int wm   = w % WM_WARPS;
    const int wn   = w / WM_WARPS;
    const int lane = tid & 31;
    const int gid  = lane >> 2;
    const int tig  = lane & 3;

    float4 acc[MF][NF];
    #pragma unroll
    for (int i = 0; i < MF; i++)
        #pragma unroll
        for (int j = 0; j < NF; j++)
            acc[i][j] = make_float4(0.f, 0.f, 0.f, 0.f);

    float4 a_st[ASEG][2];
    uint4  b_st[BSEG];

    auto ldg_tiles = [&](int k0) {
        #pragma unroll
        for (int p = 0; p < ASEG; p++) {
            const int idx = p * 256 + tid;
            const int r = idx >> 2, c8 = (idx & 3) * 8;
            a_st[p][0] = *(const float4*)&A[(size_t)(bm + r) * K + k0 + c8];
            a_st[p][1] = *(const float4*)&A[(size_t)(bm + r) * K + k0 + c8 + 4];
        }
        #pragma unroll
        for (int p = 0; p < BSEG; p++) {
            const int idx = p * 256 + tid;
            const int r = idx >> 2, c8 = (idx & 3) * 8;
            b_st[p] = *(const uint4*)&Bt[(size_t)(bn + r) * K + k0 + c8];
        }
    };
    auto sts_tiles = [&](__half* base) {
        __half* As = base;
        __half* Bs = base + BM * TS_H;
        #pragma unroll
        for (int p = 0; p < ASEG; p++) {
            const int idx = p * 256 + tid;
            const int r = idx >> 2, c8 = (idx & 3) * 8;
            __half2 h0 = __floats2half2_rn(a_st[p][0].x, a_st[p][0].y);
            __half2 h1 = __floats2half2_rn(a_st[p][0].z, a_st[p][0].w);
            __half2 h2 = __floats2half2_rn(a_st[p][1].x, a_st[p][1].y);
            __half2 h3 = __floats2half2_rn(a_st[p][1].z, a_st[p][1].w);
            uint4 v;
            v.x = *(unsigned*)&h0; v.y = *(unsigned*)&h1;
            v.z = *(unsigned*)&h2; v.w = *(unsigned*)&h3;
            *(uint4*)&As[r * TS_H + c8] = v;
        }
        #pragma unroll
        for (int p = 0; p < BSEG; p++) {
            const int idx = p * 256 + tid;
            const int r = idx >> 2, c8 = (idx & 3) * 8;
            *(uint4*)&Bs[r * TS_H + c8] = b_st[p];
        }
    };
    auto compute = [&](const __half* base) {
        const __half* As = base;
        const __half* Bs = base + BM * TS_H;
        const unsigned a_base = smem_u32(
            &As[(wm * WT_M + (lane & 15)) * TS_H + ((lane >> 4) * 8)]);
        const unsigned b_base = smem_u32(
            &Bs[(wn * WT_N + (lane & 7)) * TS_H + (((lane >> 3) & 1) * 8)]);
        #pragma unroll
        for (int ks = 0; ks < 2; ks++) {
            unsigned af[MF][4], bf[NF][2];
            #pragma unroll
            for (int mf = 0; mf < MF; mf++)
                ldsm_x4(af[mf], a_base + (mf * 16 * TS_H + ks * 16) * 2);
            #pragma unroll
            for (int nf = 0; nf < NF; nf++)
                ldsm_x2(bf[nf], b_base + (nf * 8 * TS_H + ks * 16) * 2);
            #pragma unroll
            for (int mf = 0; mf < MF; mf++)
                #pragma unroll
                for (int nf = 0; nf < NF; nf++)
                    mma_f16(acc[mf][nf],
                            af[mf][0], af[mf][1], af[mf][2], af[mf][3],
                            bf[nf][0], bf[nf][1]);
        }
    };

    const int NIT = K / BK;
    ldg_tiles(0);
    sts_tiles(sh16);
    __syncthreads();
    int cur = 0;
    for (int it = 0; it < NIT; it++) {
        if (it + 1 < NIT) ldg_tiles((it + 1) * BK);
        compute(sh16 + cur * BUFH);
        if (it + 1 < NIT) {
            sts_tiles(sh16 + (cur ^ 1) * BUFH);
            __syncthreads();
            cur ^= 1;
        }
    }

    #pragma unroll
    for (int mf = 0; mf < MF; mf++) {
        #pragma unroll
        for (int nf = 0; nf < NF; nf++) {
            const int m0 = bm + wm * WT_M + mf * 16 + gid;
            const int n0 = bn + wn * WT_N + nf * 8 + tig * 2;
            const float bs0 = bias[n0], bs1 = bias[n0 + 1];
            *(float2*)&C[(size_t)m0 * N + n0] =
                make_float2(acc[mf][nf].x + bs0, acc[mf][nf].y + bs1);
            *(float2*)&C[(size_t)(m0 + 8) * N + n0] =
                make_float2(acc[mf][nf].z + bs0, acc[mf][nf].w + bs1);
        }
    }
}

#define QKV_SMEM ((BM * TS_H + 128 * TS_H) * 2 * 2)   // 40960 B
#define OUT_SMEM ((BM * TS_H + 64 * TS_H) * 2 * 2)    // 30720 B

// ---------------------------------------------------------------------------
// Sliding-window attention, fp16 MMA + ldmatrix throughout.
// Qs [64][72]h, K [128][72]h (union with Vt [64][136]h), P [64][136]h.
// GEMM1: A=Q ldsm.x4, B=K ldsm.x2.  GEMM2: A=P ldsm.x4, B=Vt ldsm.x2.
// Softmax fp32 (scale folded into Q staging).
// ---------------------------------------------------------------------------
#define TQ 64
#define TC 128
#define QS_H 72
#define KS_H 72
#define VT_H 136
#define P_H  136
#define KV_UNION_H (TC * KS_H)                 // 9216 >= 64*136
#define ATTN_H (TQ * QS_H + KV_UNION_H + TQ * P_H)   // 22528 halves
#define ATTN_SMEM_BYTES (ATTN_H * 2)                 // 45056 B

__global__ __launch_bounds__(256, 2) void window_attn_f16(
    const float* __restrict__ qkv, float* __restrict__ out)
{
    const int s0  = blockIdx.x * TQ;
    const int h   = blockIdx.y;
    const int b   = blockIdx.z;
    const int tid = threadIdx.x;

    extern __shared__ __half sh16[];
    __half* Qs = sh16;
    __half* KV = sh16 + TQ * QS_H;
    __half* P  = KV + KV_UNION_H;

    const int w    = tid >> 5;
    const int lane = tid & 31;
    const int gid  = lane >> 2;
    const int tig  = lane & 3;
    const int wm   = w & 1;
    const int wn   = w >> 1;

    const size_t mrow = (size_t)b * SEQ;
    const int hoff = h * HD;
    const int d2 = lane * 2;

    // Stage Q (scale folded) and K as half
    for (int r = w; r < TQ; r += 8) {
        float2 qv = *(const float2*)&qkv[(mrow + s0 + r) * NQKV + hoff + d2];
        *(__half2*)&Qs[r * QS_H + d2] =
            __floats2half2_rn(qv.x * 0.125f, qv.y * 0.125f);
    }
    for (int c = w; c < TC; c += 8) {
        const int idx = s0 - WIN + c;
        float2 kv = make_float2(0.f, 0.f);
        if (idx >= 0 && idx < SEQ)
            kv = *(const float2*)&qkv[(mrow + idx) * NQKV + D_MODEL + hoff + d2];
        *(__half2*)&KV[c * KS_H + d2] = __floats2half2_rn(kv.x, kv.y);
    }
    __syncthreads();

    // ---- GEMM1: S[64][128] = Q @ K^T.  MF=2, NF=4, 4 k16-steps. ----
    {
        float4 acc[2][4];
        #pragma unroll
        for (int i = 0; i < 2; i++)
            #pragma unroll
            for (int j = 0; j < 4; j++)
                acc[i][j] = make_float4(0.f, 0.f, 0.f, 0.f);

        const unsigned a_base = smem_u32(
            &Qs[(wm * 32 + (lane & 15)) * QS_H + ((lane >> 4) * 8)]);
        const unsigned b_base = smem_u32(
            &KV[(wn * 32 + (lane & 7)) * KS_H + (((lane >> 3) & 1) * 8)]);

        #pragma unroll
        for (int ks = 0; ks < 4; ks++) {
            unsigned af[2][4], bf[4][2];
            #pragma unroll
            for (int mf = 0; mf < 2; mf++)
                ldsm_x4(af[mf], a_base + (mf * 16 * QS_H + ks * 16) * 2);
            #pragma unroll
            for (int nf = 0; nf < 4; nf++)
                ldsm_x2(bf[nf], b_base + (nf * 8 * KS_H + ks * 16) * 2);
            #pragma unroll
            for (int mf = 0; mf < 2; mf++)
                #pragma unroll
                for (int nf = 0; nf < 4; nf++)
                    mma_f16(acc[mf][nf],
                            af[mf][0], af[mf][1], af[mf][2], af[mf][3],
                            bf[nf][0], bf[nf][1]);
        }
        #pragma unroll
        for (int mf = 0; mf < 2; mf++) {
            #pragma unroll
            for (int nf = 0; nf < 4; nf++) {
                const int m0 = wm * 32 + mf * 16 + gid;
                const int n0 = wn * 32 + nf * 8 + tig * 2;
                *(__half2*)&P[m0 * P_H + n0] =
                    __floats2half2_rn(acc[mf][nf].x, acc[mf][nf].y);
                *(__half2*)&P[(m0 + 8) * P_H + n0] =
                    __floats2half2_rn(acc[mf][nf].z, acc[mf][nf].w);
            }
        }
    }
    __syncthreads();

    // Stage V transposed: Vt[d][c] (overwrites K region)
    for (int c = w; c < TC; c += 8) {
        const int idx = s0 - WIN + c;
        float v0 = 0.f, v1 = 0.f;
        if (idx >= 0 && idx < SEQ) {
            v0 = qkv[(mrow + idx) * NQKV + 2 * D_MODEL + hoff + lane];
            v1 = qkv[(mrow + idx) * NQKV + 2 * D_MODEL + hoff + lane + 32];
        }
        KV[lane * VT_H + c]        = __float2half_rn(v0);
        KV[(lane + 32) * VT_H + c] = __float2half_rn(v1);
    }

    // ---- Masked softmax (fp32), warp per row ----
    {
        for (int q = w; q < TQ; q += 8) {
            float vals[4];
            #pragma unroll
            for (int k = 0; k < 4; k++) {
                const int c = lane + k * 32;
                const int idx = s0 - WIN + c;
                const bool valid = (c >= q) && (c <= q + 2 * WIN) && (idx >= 0) && (idx < SEQ);
                vals[k] = valid ? __half2float(P[q * P_H + c]) : -1e30f;
            }
            float m = fmaxf(fmaxf(vals[0], vals[1]), fmaxf(vals[2], vals[3]));
            #pragma unroll
            for (int off = 16; off > 0; off >>= 1)
                m = fmaxf(m, __shfl_xor_sync(0xffffffffu, m, off));
            float e[4], sum = 0.f;
            #pragma unroll
            for (int k = 0; k < 4; k++) { e[k] = __expf(vals[k] - m); sum += e[k]; }
            #pragma unroll
            for (int off = 16; off > 0; off >>= 1)
                sum += __shfl_xor_sync(0xffffffffu, sum, off);
            const float inv = 1.0f / sum;
            #pragma unroll
            for (int k = 0; k < 4; k++)
                P[q * P_H + lane + k * 32] = __float2half_rn(e[k] * inv);
        }
    }
    __syncthreads();

    // ---- GEMM2: O[64][64] = P @ Vt^T.  MF=2, NF=2, 8 k16-steps. ----
    {
        float4 acc[2][2];
        #pragma unroll
        for (int i = 0; i < 2; i++)
            #pragma unroll
            for (int j = 0; j < 2; j++)
                acc[i][j] = make_float4(0.f, 0.f, 0.f, 0.f);

        const unsigned p_base = smem_u32(
            &P[(wm * 32 + (lane & 15)) * P_H + ((lane >> 4) * 8)]);
        const unsigned v_base = smem_u32(
            &KV[(wn * 16 + (lane & 7)) * VT_H + (((lane >> 3) & 1) * 8)]);

        #pragma unroll
        for (int ks = 0; ks < 8; ks++) {
            unsigned af[2][4], bf[2][2];
            #pragma unroll
            for (int mf = 0; mf < 2; mf++)
                ldsm_x4(af[mf], p_base + (mf * 16 * P_H + ks * 16) * 2);
            #pragma unroll
            for (int nf = 0; nf < 2; nf++)
                ldsm_x2(bf[nf], v_base + (nf * 8 * VT_H + ks * 16) * 2);
            #pragma unroll
            for (int mf = 0; mf < 2; mf++)
                #pragma unroll
                for (int nf = 0; nf < 2; nf++)
                    mma_f16(acc[mf][nf],
                            af[mf][0], af[mf][1], af[mf][2], af[mf][3],
                            bf[nf][0], bf[nf][1]);
        }
        #pragma unroll
        for (int mf = 0; mf < 2; mf++) {
            #pragma unroll
            for (int nf = 0; nf < 2; nf++) {
                const int m0 = wm * 32 + mf * 16 + gid;
                const int n0 = wn * 16 + nf * 8 + tig * 2;
                size_t o0 = ((size_t)b * SEQ + s0 + m0) * D_MODEL + hoff + n0;
                *(float2*)&out[o0] = make_float2(acc[mf][nf].x, acc[mf][nf].y);
                size_t o1 = ((size_t)b * SEQ + s0 + m0 + 8) * D_MODEL + hoff + n0;
                *(float2*)&out[o1] = make_float2(acc[mf][nf].z, acc[mf][nf].w);
            }
        }
    }
}

// ---------------------------------------------------------------------------
extern "C" void kernel_launch(void* const* d_in, const int* in_sizes, int n_in,
                              void* d_out, int out_size)
{
    const float* x     = (const float*)d_in[0];
    const float* w_qkv = (const float*)d_in[1];
    const float* b_qkv = (const float*)d_in[2];
    const float* w_out = (const float*)d_in[3];
    const float* b_out = (const float*)d_in[4];
    float* out = (float*)d_out;

    float *qkv, *attn;
    __half *wqt, *wot;
    cudaGetSymbolAddress((void**)&qkv,  g_qkv);
    cudaGetSymbolAddress((void**)&attn, g_attn);
    cudaGetSymbolAddress((void**)&wqt,  g_wqkv_t);
    cudaGetSymbolAddress((void**)&wot,  g_wout_t);

    cudaFuncSetAttribute(gemm_f16<128>,
                         cudaFuncAttributeMaxDynamicSharedMemorySize, QKV_SMEM);
    cudaFuncSetAttribute(gemm_f16<64>,
                         cudaFuncAttributeMaxDynamicSharedMemorySize, OUT_SMEM);
    cudaFuncSetAttribute(window_attn_f16,
                         cudaFuncAttributeMaxDynamicSharedMemorySize, ATTN_SMEM_BYTES);

    // 0) Pre-transpose weights to [n][k] half
    {
        dim3 g1(NQKV / 32, D_MODEL / 32);
        transpose_wh<<<g1, 256>>>(w_qkv, wqt, D_MODEL, NQKV);
        dim3 g2(D_MODEL / 32, D_MODEL / 32);
        transpose_wh<<<g2, 256>>>(w_out, wot, D_MODEL, D_MODEL);
    }
    // 1) QKV projection (fp16 MMA)
    {
        dim3 grid(NQKV / 128, MTOT / BM);         // 12 x 32
        gemm_f16<128><<<grid, 256, QKV_SMEM>>>(
            x, wqt, b_qkv, qkv, MTOT, NQKV, D_MODEL);
    }
    // 2) Windowed attention (fp16 MMA)
    {
        dim3 grid(SEQ / TQ, NHEAD, BATCH);        // 512 CTAs
        window_attn_f16<<<grid, 256, ATTN_SMEM_BYTES>>>(qkv, attn);
    }
    // 3) Output projection (fp16 MMA)
    {
        dim3 grid(D_MODEL / 64, MTOT / BM);       // 256 CTAs
        gemm_f16<64><<<grid, 256, OUT_SMEM>>>(
            attn, wot, b_out, out, MTOT, D_MODEL, D_MODEL);
    }
}

// round 14
// speedup vs baseline: 1.9932x; 1.3154x over previous
#include <cuda_runtime.h>
#include <cuda_fp16.h>
#include <cstdint>
#include <math.h>

#define D_MODEL 512
#define NHEAD   8
#define HD      64
#define WIN     32
#define BATCH   2
#define SEQ     2048
#define MTOT    (BATCH * SEQ)          // 4096
#define NQKV    (3 * D_MODEL)          // 1536

// Scratch (no cudaMalloc allowed)
__device__ __half g_qkv[MTOT * NQKV];            // [m][1536] half
__device__ __half g_wqkv_t[NQKV * D_MODEL];      // w_qkv^T [n][k] half
__device__ __half g_wout_t[D_MODEL * D_MODEL];   // w_out^T [n][k] half
__device__ __half g_attn[MTOT * D_MODEL];        // [m][512] half

__device__ __forceinline__ unsigned smem_u32(const void* p) {
    return (unsigned)__cvta_generic_to_shared(p);
}
__device__ __forceinline__ void ldsm_x4(unsigned int* r, unsigned addr) {
    asm volatile("ldmatrix.sync.aligned.m8n8.x4.shared.b16 {%0,%1,%2,%3}, [%4];"
        : "=r"(r[0]), "=r"(r[1]), "=r"(r[2]), "=r"(r[3]) : "r"(addr));
}
__device__ __forceinline__ void ldsm_x2(unsigned int* r, unsigned addr) {
    asm volatile("ldmatrix.sync.aligned.m8n8.x2.shared.b16 {%0,%1}, [%2];"
        : "=r"(r[0]), "=r"(r[1]) : "r"(addr));
}
__device__ __forceinline__ void ldsm_x2_trans(unsigned int* r, unsigned addr) {
    asm volatile("ldmatrix.sync.aligned.m8n8.x2.trans.shared.b16 {%0,%1}, [%2];"
        : "=r"(r[0]), "=r"(r[1]) : "r"(addr));
}
__device__ __forceinline__ void mma_f16(float4& d,
    unsigned a0, unsigned a1, unsigned a2, unsigned a3,
    unsigned b0, unsigned b1)
{
    asm volatile(
        "mma.sync.aligned.m16n8k16.row.col.f32.f16.f16.f32 "
        "{%0,%1,%2,%3}, {%4,%5,%6,%7}, {%8,%9}, {%0,%1,%2,%3};\n"
        : "+f"(d.x), "+f"(d.y), "+f"(d.z), "+f"(d.w)
        : "r"(a0), "r"(a1), "r"(a2), "r"(a3), "r"(b0), "r"(b1));
}
// 16B cp.async with zero-fill when src_sz == 0
__device__ __forceinline__ void cp16(unsigned dst, const void* src, int src_sz) {
    asm volatile("cp.async.cg.shared.global [%0], [%1], 16, %2;"
        :: "r"(dst), "l"(src), "r"(src_sz) : "memory");
}
__device__ __forceinline__ void cp_commit_wait0() {
    asm volatile("cp.async.commit_group;" ::: "memory");
    asm volatile("cp.async.wait_group 0;" ::: "memory");
}

// ---------------------------------------------------------------------------
// Weight transpose: w[k][n] f32 -> wt[n][k] half.  32x32 tiles.
// ---------------------------------------------------------------------------
__global__ __launch_bounds__(256) void transpose_wh(
    const float* __restrict__ w, __half* __restrict__ wt, int K, int N)
{
    __shared__ float t[32][33];
    const int bx = blockIdx.x * 32;
    const int by = blockIdx.y * 32;
    const int x = threadIdx.x & 31;
    const int y0 = threadIdx.x >> 5;
    #pragma unroll
    for (int j = 0; j < 32; j += 8)
        t[y0 + j][x] = w[(size_t)(by + y0 + j) * N + bx + x];
    __syncthreads();
    #pragma unroll
    for (int j = 0; j < 32; j += 8)
        wt[(size_t)(bx + y0 + j) * K + by + x] = __float2half_rn(t[x][y0 + j]);
}

// ---------------------------------------------------------------------------
// FP16 tensor-core GEMM, double-buffered: C[M,N] = A @ Bt^T + bias (C half).
// AHALF: A is half [m][k] (uint4 path); else f32 [m][k] (convert on STS).
// ---------------------------------------------------------------------------
#define BM 128
#define BK 32
#define TS_H 40

template<int BN_, bool AHALF>
__global__ __launch_bounds__(256, 2) void gemm_f16(
    const void* __restrict__ Ain, const __half* __restrict__ Bt,
    const float* __restrict__ bias, __half* __restrict__ C,
    int M, int N, int K)
{
    constexpr int WM_WARPS = (BN_ == 128) ? 2 : 4;
    constexpr int WT_M = BM / WM_WARPS;
    constexpr int WT_N = BN_ / (8 / WM_WARPS);
    constexpr int MF = WT_M / 16;
    constexpr int NF = WT_N / 8;
    constexpr int BUFH = BM * TS_H + BN_ * TS_H;
    constexpr int ASEG = 2;
    constexpr int BSEG = (BN_ * BK) / 2048;

    extern __shared__ __half sh16[];

    const int tid  = threadIdx.x;
    const int bm   = blockIdx.y * BM;
    const int bn   = blockIdx.x * BN_;
    const int w    = tid >> 5;
    const int wm   = w % WM_WARPS;
    const int wn   = w / WM_WARPS;
    const int lane = tid & 31;
    const int gid  = lane >> 2;
    const int tig  = lane & 3;

    float4 acc[MF][NF];
    #pragma unroll
    for (int i = 0; i < MF; i++)
        #pragma unroll
        for (int j = 0; j < NF; j++)
            acc[i][j] = make_float4(0.f, 0.f, 0.f, 0.f);

    float4 a_f32[ASEG][2];
    uint4  a_h16[ASEG];
    uint4  b_st[BSEG];

    auto ldg_tiles = [&](int k0) {
        #pragma unroll
        for (int p = 0; p < ASEG; p++) {
            const int idx = p * 256 + tid;
            const int r = idx >> 2, c8 = (idx & 3) * 8;
            if (AHALF) {
                a_h16[p] = *(const uint4*)&((const __half*)Ain)[(size_t)(bm + r) * K + k0 + c8];
            } else {
                a_f32[p][0] = *(const float4*)&((const float*)Ain)[(size_t)(bm + r) * K + k0 + c8];
                a_f32[p][1] = *(const float4*)&((const float*)Ain)[(size_t)(bm + r) * K + k0 + c8 + 4];
            }
        }
        #pragma unroll
        for (int p = 0; p < BSEG; p++) {
            const int idx = p * 256 + tid;
            const int r = idx >> 2, c8 = (idx & 3) * 8;
            b_st[p] = *(const uint4*)&Bt[(size_t)(bn + r) * K + k0 + c8];
        }
    };
    auto sts_tiles = [&](__half* base) {
        __half* As = base;
        __half* Bs = base + BM * TS_H;
        #pragma unroll
        for (int p = 0; p < ASEG; p++) {
            const int idx = p * 256 + tid;
            const int r = idx >> 2, c8 = (idx & 3) * 8;
            if (AHALF) {
                *(uint4*)&As[r * TS_H + c8] = a_h16[p];
            } else {
                __half2 h0 = __floats2half2_rn(a_f32[p][0].x, a_f32[p][0].y);
                __half2 h1 = __floats2half2_rn(a_f32[p][0].z, a_f32[p][0].w);
                __half2 h2 = __floats2half2_rn(a_f32[p][1].x, a_f32[p][1].y);
                __half2 h3 = __floats2half2_rn(a_f32[p][1].z, a_f32[p][1].w);
                uint4 v;
                v.x = *(unsigned*)&h0; v.y = *(unsigned*)&h1;
                v.z = *(unsigned*)&h2; v.w = *(unsigned*)&h3;
                *(uint4*)&As[r * TS_H + c8] = v;
            }
        }
        #pragma unroll
        for (int p = 0; p < BSEG; p++) {
            const int idx = p * 256 + tid;
            const int r = idx >> 2, c8 = (idx & 3) * 8;
            *(uint4*)&Bs[r * TS_H + c8] = b_st[p];
        }
    };
    auto compute = [&](const __half* base) {
        const __half* As = base;
        const __half* Bs = base + BM * TS_H;
        const unsigned a_base = smem_u32(
            &As[(wm * WT_M + (lane & 15)) * TS_H + ((lane >> 4) * 8)]);
        const unsigned b_base = smem_u32(
            &Bs[(wn * WT_N + (lane & 7)) * TS_H + (((lane >> 3) & 1) * 8)]);
        #pragma unroll
        for (int ks = 0; ks < 2; ks++) {
            unsigned af[MF][4], bf[NF][2];
            #pragma unroll
            for (int mf = 0; mf < MF; mf++)
                ldsm_x4(af[mf], a_base + (mf * 16 * TS_H + ks * 16) * 2);
            #pragma unroll
            for (int nf = 0; nf < NF; nf++)
                ldsm_x2(bf[nf], b_base + (nf * 8 * TS_H + ks * 16) * 2);
            #pragma unroll
            for (int mf = 0; mf < MF; mf++)
                #pragma unroll
                for (int nf = 0; nf < NF; nf++)
                    mma_f16(acc[mf][nf],
                            af[mf][0], af[mf][1], af[mf][2], af[mf][3],
                            bf[nf][0], bf[nf][1]);
        }
    };

    const int NIT = K / BK;
    ldg_tiles(0);
    sts_tiles(sh16);
    __syncthreads();
    int cur = 0;
    for (int it = 0; it < NIT; it++) {
        if (it + 1 < NIT) ldg_tiles((it + 1) * BK);
        compute(sh16 + cur * BUFH);
        if (it + 1 < NIT) {
            sts_tiles(sh16 + (cur ^ 1) * BUFH);
            __syncthreads();
            cur ^= 1;
        }
    }

    #pragma unroll
    for (int mf = 0; mf < MF; mf++) {
        #pragma unroll
        for (int nf = 0; nf < NF; nf++) {
            const int m0 = bm + wm * WT_M + mf * 16 + gid;
            const int n0 = bn + wn * WT_N + nf * 8 + tig * 2;
            const float bs0 = bias[n0], bs1 = bias[n0 + 1];
            *(__half2*)&C[(size_t)m0 * N + n0] =
                __floats2half2_rn(acc[mf][nf].x + bs0, acc[mf][nf].y + bs1);
            *(__half2*)&C[(size_t)(m0 + 8) * N + n0] =
                __floats2half2_rn(acc[mf][nf].z + bs0, acc[mf][nf].w + bs1);
        }
    }
}

#define QKV_SMEM ((BM * TS_H + 128 * TS_H) * 2 * 2)   // 40960 B
#define OUT_SMEM ((BM * TS_H + 64 * TS_H) * 2 * 2)    // 30720 B

// ---------------------------------------------------------------------------
// Sliding-window attention: cp.async burst staging, fp16 MMA, ldsm.trans V.
// Qs [64][72]h, K [128][72]h, V [128][72]h (natural [c][d]), P [64][136]h.
// Scale 1/8 applied in fp32 softmax.
// ---------------------------------------------------------------------------
#define TQ 64
#define TC 128
#define QS_H 72
#define KS_H 72
#define VS_H 72
#define P_H  136
#define ATTN_H (TQ * QS_H + TC * KS_H + TC * VS_H + TQ * P_H)  // 31744
#define ATTN_SMEM_BYTES (ATTN_H * 2)                           // 63488

__global__ __launch_bounds__(256, 2) void window_attn_f16(
    const __half* __restrict__ qkv, __half* __restrict__ out)
{
    const int s0  = blockIdx.x * TQ;
    const int h   = blockIdx.y;
    const int b   = blockIdx.z;
    const int tid = threadIdx.x;

    extern __shared__ __half sh16[];
    __half* Qs = sh16;
    __half* Ks = Qs + TQ * QS_H;
    __half* Vs = Ks + TC * KS_H;
    __half* P  = Vs + TC * VS_H;

    const int w    = tid >> 5;
    const int lane = tid & 31;
    const int gid  = lane >> 2;
    const int tig  = lane & 3;
    const int wm   = w & 1;
    const int wn   = w >> 1;

    const size_t mrow = (size_t)b * SEQ;
    const int hoff = h * HD;

    // ---- cp.async staging burst: Q (512 chunks) + K (1024) + V (1024) ----
    {
        // Q: row r, chunk ch (8 chunks of 8 halves per row)
        #pragma unroll
        for (int p = 0; p < 2; p++) {
            const int q = p * 256 + tid;
            const int r = q >> 3, ch = (q & 7) * 8;
            cp16(smem_u32(&Qs[r * QS_H + ch]),
                 &qkv[(mrow + s0 + r) * NQKV + hoff + ch], 16);
        }
        #pragma unroll
        for (int p = 0; p < 4; p++) {
            const int q = p * 256 + tid;
            const int r = q >> 3, ch = (q & 7) * 8;
            const int idx = s0 - WIN + r;
            const bool v = (idx >= 0) && (idx < SEQ);
            const int idxc = v ? idx : 0;
            cp16(smem_u32(&Ks[r * KS_H + ch]),
                 &qkv[(mrow + idxc) * NQKV + D_MODEL + hoff + ch], v ? 16 : 0);
        }
        #pragma unroll
        for (int p = 0; p < 4; p++) {
            const int q = p * 256 + tid;
            const int r = q >> 3, ch = (q & 7) * 8;
            const int idx = s0 - WIN + r;
            const bool v = (idx >= 0) && (idx < SEQ);
            const int idxc = v ? idx : 0;
            cp16(smem_u32(&Vs[r * VS_H + ch]),
                 &qkv[(mrow + idxc) * NQKV + 2 * D_MODEL + hoff + ch], v ? 16 : 0);
        }
        cp_commit_wait0();
    }
    __syncthreads();

    // ---- GEMM1: S[64][128] = Q @ K^T ----
    {
        float4 acc[2][4];
        #pragma unroll
        for (int i = 0; i < 2; i++)
            #pragma unroll
            for (int j = 0; j < 4; j++)
                acc[i][j] = make_float4(0.f, 0.f, 0.f, 0.f);

        const unsigned a_base = smem_u32(
            &Qs[(wm * 32 + (lane & 15)) * QS_H + ((lane >> 4) * 8)]);
        const unsigned b_base = smem_u32(
            &Ks[(wn * 32 + (lane & 7)) * KS_H + (((lane >> 3) & 1) * 8)]);

        #pragma unroll
        for (int ks = 0; ks < 4; ks++) {
            unsigned af[2][4], bf[4][2];
            #pragma unroll
            for (int mf = 0; mf < 2; mf++)
                ldsm_x4(af[mf], a_base + (mf * 16 * QS_H + ks * 16) * 2);
            #pragma unroll
            for (int nf = 0; nf < 4; nf++)
                ldsm_x2(bf[nf], b_base + (nf * 8 * KS_H + ks * 16) * 2);
            #pragma unroll
            for (int mf = 0; mf < 2; mf++)
                #pragma unroll
                for (int nf = 0; nf < 4; nf++)
                    mma_f16(acc[mf][nf],
                            af[mf][0], af[mf][1], af[mf][2], af[mf][3],
                            bf[nf][0], bf[nf][1]);
        }
        #pragma unroll
        for (int mf = 0; mf < 2; mf++) {
            #pragma unroll
            for (int nf = 0; nf < 4; nf++) {
                const int m0 = wm * 32 + mf * 16 + gid;
                const int n0 = wn * 32 + nf * 8 + tig * 2;
                *(__half2*)&P[m0 * P_H + n0] =
                    __floats2half2_rn(acc[mf][nf].x, acc[mf][nf].y);
                *(__half2*)&P[(m0 + 8) * P_H + n0] =
                    __floats2half2_rn(acc[mf][nf].z, acc[mf][nf].w);
            }
        }
    }
    __syncthreads();

    // ---- Masked softmax (fp32, scale 1/8 applied here), warp per row ----
    {
        for (int q = w; q < TQ; q += 8) {
            float vals[4];
            #pragma unroll
            for (int k = 0; k < 4; k++) {
                const int c = lane + k * 32;
                const int idx = s0 - WIN + c;
                const bool valid = (c >= q) && (c <= q + 2 * WIN) && (idx >= 0) && (idx < SEQ);
                vals[k] = valid ? __half2float(P[q * P_H + c]) * 0.125f : -1e30f;
            }
            float m = fmaxf(fmaxf(vals[0], vals[1]), fmaxf(vals[2], vals[3]));
            #pragma unroll
            for (int off = 16; off > 0; off >>= 1)
                m = fmaxf(m, __shfl_xor_sync(0xffffffffu, m, off));
            float e[4], sum = 0.f;
            #pragma unroll
            for (int k = 0; k < 4; k++) { e[k] = __expf(vals[k] - m); sum += e[k]; }
            #pragma unroll
            for (int off = 16; off > 0; off >>= 1)
                sum += __shfl_xor_sync(0xffffffffu, sum, off);
            const float inv = 1.0f / sum;
            #pragma unroll
            for (int k = 0; k < 4; k++)
                P[q * P_H + lane + k * 32] = __float2half_rn(e[k] * inv);
        }
    }
    __syncthreads();

    // ---- GEMM2: O[64][64] = P @ V.  B-frags via ldmatrix.trans on V[c][d]. ----
    {
        float4 acc[2][2];
        #pragma unroll
        for (int i = 0; i < 2; i++)
            #pragma unroll
            for (int j = 0; j < 2; j++)
                acc[i][j] = make_float4(0.f, 0.f, 0.f, 0.f);

        const unsigned p_base = smem_u32(
            &P[(wm * 32 + (lane & 15)) * P_H + ((lane >> 4) * 8)]);
        const int l2 = lane & 15;

        #pragma unroll
        for (int ks = 0; ks < 8; ks++) {
            unsigned af[2][4], bf[2][2];
            #pragma unroll
            for (int mf = 0; mf < 2; mf++)
                ldsm_x4(af[mf], p_base + (mf * 16 * P_H + ks * 16) * 2);
            #pragma unroll
            for (int nf = 0; nf < 2; nf++) {
                const int nb = wn * 16 + nf * 8;
                const unsigned v_addr = smem_u32(
                    &Vs[(ks * 16 + l2) * VS_H + nb]);
                ldsm_x2_trans(bf[nf], v_addr);
            }
            #pragma unroll
            for (int mf = 0; mf < 2; mf++)
                #pragma unroll
                for (int nf = 0; nf < 2; nf++)
                    mma_f16(acc[mf][nf],
                            af[mf][0], af[mf][1], af[mf][2], af[mf][3],
                            bf[nf][0], bf[nf][1]);
        }
        #pragma unroll
        for (int mf = 0; mf < 2; mf++) {
            #pragma unroll
            for (int nf = 0; nf < 2; nf++) {
                const int m0 = wm * 32 + mf * 16 + gid;
                const int n0 = wn * 16 + nf * 8 + tig * 2;
                size_t o0 = ((size_t)b * SEQ + s0 + m0) * D_MODEL + hoff + n0;
                *(__half2*)&out[o0] = __floats2half2_rn(acc[mf][nf].x, acc[mf][nf].y);
                size_t o1 = ((size_t)b * SEQ + s0 + m0 + 8) * D_MODEL + hoff + n0;
                *(__half2*)&out[o1] = __floats2half2_rn(acc[mf][nf].z, acc[mf][nf].w);
            }
        }
    }
}

// ---------------------------------------------------------------------------
// Final output projection writes f32 (harness output dtype).
// ---------------------------------------------------------------------------
template<int BN_>
__global__ __launch_bounds__(256, 2) void gemm_f16_outf32(
    const __half* __restrict__ A, const __half* __restrict__ Bt,
    const float* __restrict__ bias, float* __restrict__ C,
    int M, int N, int K)
{
    constexpr int WM_WARPS = 4;
    constexpr int WT_M = BM / WM_WARPS;          // 32
    constexpr int WT_N = BN_ / (8 / WM_WARPS);   // 32
    constexpr int MF = WT_M / 16;                // 2
    constexpr int NF = WT_N / 8;                 // 4
    constexpr int BUFH = BM * TS_H + BN_ * TS_H;
    constexpr int ASEG = 2;
    constexpr int BSEG = (BN_ * BK) / 2048;      // 1

    extern __shared__ __half sh16[];

    const int tid  = threadIdx.x;
    const int bm   = blockIdx.y * BM;
    const int bn   = blockIdx.x * BN_;
    const int w    = tid >> 5;
    const int wm   = w % WM_WARPS;
    const int wn   = w / WM_WARPS;
    const int lane = tid & 31;
    const int gid  = lane >> 2;
    const int tig  = lane & 3;

    float4 acc[MF][NF];
    #pragma unroll
    for (int i = 0; i < MF; i++)
        #pragma unroll
        for (int j = 0; j < NF; j++)
            acc[i][j] = make_float4(0.f, 0.f, 0.f, 0.f);

    uint4 a_st[ASEG], b_st[BSEG];

    auto ldg_tiles = [&](int k0) {
        #pragma unroll
        for (int p = 0; p < ASEG; p++) {
            const int idx = p * 256 + tid;
            const int r = idx >> 2, c8 = (idx & 3) * 8;
            a_st[p] = *(const uint4*)&A[(size_t)(bm + r) * K + k0 + c8];
        }
        #pragma unroll
        for (int p = 0; p < BSEG; p++) {
            const int idx = p * 256 + tid;
            const int r = idx >> 2, c8 = (idx & 3) * 8;
            b_st[p] = *(const uint4*)&Bt[(size_t)(bn + r) * K + k0 + c8];
        }
    };
    auto sts_tiles = [&](__half* base) {
        __half* As = base;
        __half* Bs = base + BM * TS_H;
        #pragma unroll
        for (int p = 0; p < ASEG; p++) {
            const int idx = p * 256 + tid;
            const int r = idx >> 2, c8 = (idx & 3) * 8;
            *(uint4*)&As[r * TS_H + c8] = a_st[p];
        }
        #pragma unroll
        for (int p = 0; p < BSEG; p++) {
            const int idx = p * 256 + tid;
            const int r = idx >> 2, c8 = (idx & 3) * 8;
            *(uint4*)&Bs[r * TS_H + c8] = b_st[p];
        }
    };
    auto compute = [&](const __half* base) {
        const __half* As = base;
        const __half* Bs = base + BM * TS_H;
        const unsigned a_base = smem_u32(
            &As[(wm * WT_M + (lane & 15)) * TS_H + ((lane >> 4) * 8)]);
        const unsigned b_base = smem_u32(
            &Bs[(wn * WT_N + (lane & 7)) * TS_H + (((lane >> 3) & 1) * 8)]);
        #pragma unroll
        for (int ks = 0; ks < 2; ks++) {
            unsigned af[MF][4], bf[NF][2];
            #pragma unroll
            for (int mf = 0; mf < MF; mf++)
                ldsm_x4(af[mf], a_base + (mf * 16 * TS_H + ks * 16) * 2);
            #pragma unroll
            for (int nf = 0; nf < NF; nf++)
                ldsm_x2(bf[nf], b_base + (nf * 8 * TS_H + ks * 16) * 2);
            #pragma unroll
            for (int mf = 0; mf < MF; mf++)
                #pragma unroll
                for (int nf = 0; nf < NF; nf++)
                    mma_f16(acc[mf][nf],
                            af[mf][0], af[mf][1], af[mf][2], af[mf][3],
                            bf[nf][0], bf[nf][1]);
        }
    };

    const int NIT = K / BK;
    ldg_tiles(0);
    sts_tiles(sh16);
    __syncthreads();
    int cur = 0;
    for (int it = 0; it < NIT; it++) {
        if (it + 1 < NIT) ldg_tiles((it + 1) * BK);
        compute(sh16 + cur * BUFH);
        if (it + 1 < NIT) {
            sts_tiles(sh16 + (cur ^ 1) * BUFH);
            __syncthreads();
            cur ^= 1;
        }
    }

    #pragma unroll
    for (int mf = 0; mf < MF; mf++) {
        #pragma unroll
        for (int nf = 0; nf < NF; nf++) {
            const int m0 = bm + wm * WT_M + mf * 16 + gid;
            const int n0 = bn + wn * WT_N + nf * 8 + tig * 2;
            const float bs0 = bias[n0], bs1 = bias[n0 + 1];
            *(float2*)&C[(size_t)m0 * N + n0] =
                make_float2(acc[mf][nf].x + bs0, acc[mf][nf].y + bs1);
            *(float2*)&C[(size_t)(m0 + 8) * N + n0] =
                make_float2(acc[mf][nf].z + bs0, acc[mf][nf].w + bs1);
        }
    }
}

// ---------------------------------------------------------------------------
extern "C" void kernel_launch(void* const* d_in, const int* in_sizes, int n_in,
                              void* d_out, int out_size)
{
    const float* x     = (const float*)d_in[0];
    const float* w_qkv = (const float*)d_in[1];
    const float* b_qkv = (const float*)d_in[2];
    const float* w_out = (const float*)d_in[3];
    const float* b_out = (const float*)d_in[4];
    float* out = (float*)d_out;

    __half *qkv, *attn, *wqt, *wot;
    cudaGetSymbolAddress((void**)&qkv,  g_qkv);
    cudaGetSymbolAddress((void**)&attn, g_attn);
    cudaGetSymbolAddress((void**)&wqt,  g_wqkv_t);
    cudaGetSymbolAddress((void**)&wot,  g_wout_t);

    cudaFuncSetAttribute((const void*)gemm_f16<128, false>,
                         cudaFuncAttributeMaxDynamicSharedMemorySize, QKV_SMEM);
    cudaFuncSetAttribute((const void*)gemm_f16_outf32<64>,
                         cudaFuncAttributeMaxDynamicSharedMemorySize, OUT_SMEM);
    cudaFuncSetAttribute(window_attn_f16,
                         cudaFuncAttributeMaxDynamicSharedMemorySize, ATTN_SMEM_BYTES);

    // 0) Pre-transpose weights to [n][k] half
    {
        dim3 g1(NQKV / 32, D_MODEL / 32);
        transpose_wh<<<g1, 256>>>(w_qkv, wqt, D_MODEL, NQKV);
        dim3 g2(D_MODEL / 32, D_MODEL / 32);
        transpose_wh<<<g2, 256>>>(w_out, wot, D_MODEL, D_MODEL);
    }
    // 1) QKV projection (fp16 MMA, half output)
    {
        dim3 grid(NQKV / 128, MTOT / BM);
        gemm_f16<128, false><<<grid, 256, QKV_SMEM>>>(
            x, wqt, b_qkv, qkv, MTOT, NQKV, D_MODEL);
    }
    // 2) Windowed attention (cp.async staging, fp16 MMA, half output)
    {
        dim3 grid(SEQ / TQ, NHEAD, BATCH);
        window_attn_f16<<<grid, 256, ATTN_SMEM_BYTES>>>(qkv, attn);
    }
    // 3) Output projection (half A, f32 output)
    {
        dim3 grid(D_MODEL / 64, MTOT / BM);
        gemm_f16_outf32<64><<<grid, 256, OUT_SMEM>>>(
            attn, wot, b_out, out, MTOT, D_MODEL, D_MODEL);
    }
}

// round 15
// speedup vs baseline: 2.1189x; 1.0631x over previous
#include <cuda_runtime.h>
#include <cuda_fp16.h>
#include <cstdint>
#include <math.h>

#define D_MODEL 512
#define NHEAD   8
#define HD      64
#define WIN     32
#define BATCH   2
#define SEQ     2048
#define MTOT    (BATCH * SEQ)          // 4096
#define NQKV    (3 * D_MODEL)          // 1536

// Scratch (no cudaMalloc allowed)
__device__ __half g_xh[MTOT * D_MODEL];          // x as half
__device__ __half g_qkv[MTOT * NQKV];            // [m][1536] half
__device__ __half g_wqkv_t[NQKV * D_MODEL];      // w_qkv^T [n][k] half
__device__ __half g_wout_t[D_MODEL * D_MODEL];   // w_out^T [n][k] half
__device__ __half g_attn[MTOT * D_MODEL];        // [m][512] half

__device__ __forceinline__ unsigned smem_u32(const void* p) {
    return (unsigned)__cvta_generic_to_shared(p);
}
__device__ __forceinline__ void ldsm_x4(unsigned int* r, unsigned addr) {
    asm volatile("ldmatrix.sync.aligned.m8n8.x4.shared.b16 {%0,%1,%2,%3}, [%4];"
        : "=r"(r[0]), "=r"(r[1]), "=r"(r[2]), "=r"(r[3]) : "r"(addr));
}
__device__ __forceinline__ void ldsm_x2(unsigned int* r, unsigned addr) {
    asm volatile("ldmatrix.sync.aligned.m8n8.x2.shared.b16 {%0,%1}, [%2];"
        : "=r"(r[0]), "=r"(r[1]) : "r"(addr));
}
__device__ __forceinline__ void ldsm_x2_trans(unsigned int* r, unsigned addr) {
    asm volatile("ldmatrix.sync.aligned.m8n8.x2.trans.shared.b16 {%0,%1}, [%2];"
        : "=r"(r[0]), "=r"(r[1]) : "r"(addr));
}
__device__ __forceinline__ void mma_f16(float4& d,
    unsigned a0, unsigned a1, unsigned a2, unsigned a3,
    unsigned b0, unsigned b1)
{
    asm volatile(
        "mma.sync.aligned.m16n8k16.row.col.f32.f16.f16.f32 "
        "{%0,%1,%2,%3}, {%4,%5,%6,%7}, {%8,%9}, {%0,%1,%2,%3};\n"
        : "+f"(d.x), "+f"(d.y), "+f"(d.z), "+f"(d.w)
        : "r"(a0), "r"(a1), "r"(a2), "r"(a3), "r"(b0), "r"(b1));
}
__device__ __forceinline__ void cp16(unsigned dst, const void* src, int src_sz) {
    asm volatile("cp.async.cg.shared.global [%0], [%1], 16, %2;"
        :: "r"(dst), "l"(src), "r"(src_sz) : "memory");
}
__device__ __forceinline__ void cp_commit() {
    asm volatile("cp.async.commit_group;" ::: "memory");
}
template<int N>
__device__ __forceinline__ void cp_wait() {
    asm volatile("cp.async.wait_group %0;" :: "n"(N) : "memory");
}

// ---------------------------------------------------------------------------
// Fused prep: [0,768) w_qkv^T tiles, [768,1024) w_out^T tiles,
// [1024,2048) x f32->half conversion.
// ---------------------------------------------------------------------------
__global__ __launch_bounds__(256) void prep(
    const float* __restrict__ w_qkv, const float* __restrict__ w_out,
    const float* __restrict__ x,
    __half* __restrict__ wqt, __half* __restrict__ wot, __half* __restrict__ xh)
{
    const int bid = blockIdx.x;
    if (bid < 1024) {
        // Transpose task
        const float* w; __half* wt; int K, N, bx, by;
        if (bid < 768) { w = w_qkv; wt = wqt; K = D_MODEL; N = NQKV;
                         bx = (bid % 48) * 32; by = (bid / 48) * 32; }
        else { int b2 = bid - 768; w = w_out; wt = wot; K = D_MODEL; N = D_MODEL;
               bx = (b2 % 16) * 32; by = (b2 / 16) * 32; }
        __shared__ float t[32][33];
        const int xx = threadIdx.x & 31;
        const int y0 = threadIdx.x >> 5;
        #pragma unroll
        for (int j = 0; j < 32; j += 8)
            t[y0 + j][xx] = w[(size_t)(by + y0 + j) * N + bx + xx];
        __syncthreads();
        #pragma unroll
        for (int j = 0; j < 32; j += 8)
            wt[(size_t)(bx + y0 + j) * K + by + xx] = __float2half_rn(t[xx][y0 + j]);
    } else {
        // x conversion: 2048 elements per block
        const size_t base = (size_t)(bid - 1024) * 2048 + threadIdx.x * 8;
        float4 f0 = *(const float4*)&x[base];
        float4 f1 = *(const float4*)&x[base + 4];
        __half2 h0 = __floats2half2_rn(f0.x, f0.y);
        __half2 h1 = __floats2half2_rn(f0.z, f0.w);
        __half2 h2 = __floats2half2_rn(f1.x, f1.y);
        __half2 h3 = __floats2half2_rn(f1.z, f1.w);
        uint4 v;
        v.x = *(unsigned*)&h0; v.y = *(unsigned*)&h1;
        v.z = *(unsigned*)&h2; v.w = *(unsigned*)&h3;
        *(uint4*)&xh[base] = v;
    }
}

// ---------------------------------------------------------------------------
// All-half fp16 GEMM with cp.async 2-stage pipeline.
// C[M,N] = A[m][k] @ Bt[n][k]^T + bias.  F32OUT selects output dtype.
// BM=128, BK=32, 256 threads = 8 warps.
// ---------------------------------------------------------------------------
#define BM 128
#define BK 32
#define TS_H 40

template<int BN_, bool F32OUT>
__global__ __launch_bounds__(256, 2) void gemm_h(
    const __half* __restrict__ A, const __half* __restrict__ Bt,
    const float* __restrict__ bias, void* __restrict__ Cv,
    int M, int N, int K)
{
    constexpr int WM_WARPS = (BN_ == 128) ? 2 : 4;
    constexpr int WT_M = BM / WM_WARPS;
    constexpr int WT_N = BN_ / (8 / WM_WARPS);
    constexpr int MF = WT_M / 16;
    constexpr int NF = WT_N / 8;
    constexpr int BUFH = BM * TS_H + BN_ * TS_H;
    constexpr int BSEG = BN_ / 64;               // B chunks per thread

    extern __shared__ __half sh16[];

    const int tid  = threadIdx.x;
    const int bm   = blockIdx.y * BM;
    const int bn   = blockIdx.x * BN_;
    const int w    = tid >> 5;
    const int wm   = w % WM_WARPS;
    const int wn   = w / WM_WARPS;
    const int lane = tid & 31;
    const int gid  = lane >> 2;
    const int tig  = lane & 3;

    float4 acc[MF][NF];
    #pragma unroll
    for (int i = 0; i < MF; i++)
        #pragma unroll
        for (int j = 0; j < NF; j++)
            acc[i][j] = make_float4(0.f, 0.f, 0.f, 0.f);

    auto stage = [&](int k0, __half* base) {
        __half* As = base;
        __half* Bs = base + BM * TS_H;
        #pragma unroll
        for (int p = 0; p < 2; p++) {
            const int idx = p * 256 + tid;
            const int r = idx >> 2, c8 = (idx & 3) * 8;
            cp16(smem_u32(&As[r * TS_H + c8]),
                 &A[(size_t)(bm + r) * K + k0 + c8], 16);
        }
        #pragma unroll
        for (int p = 0; p < BSEG; p++) {
            const int idx = p * 256 + tid;
            const int r = idx >> 2, c8 = (idx & 3) * 8;
            cp16(smem_u32(&Bs[r * TS_H + c8]),
                 &Bt[(size_t)(bn + r) * K + k0 + c8], 16);
        }
        cp_commit();
    };
    auto compute = [&](const __half* base) {
        const __half* As = base;
        const __half* Bs = base + BM * TS_H;
        const unsigned a_base = smem_u32(
            &As[(wm * WT_M + (lane & 15)) * TS_H + ((lane >> 4) * 8)]);
        const unsigned b_base = smem_u32(
            &Bs[(wn * WT_N + (lane & 7)) * TS_H + (((lane >> 3) & 1) * 8)]);
        #pragma unroll
        for (int ks = 0; ks < 2; ks++) {
            unsigned af[MF][4], bf[NF][2];
            #pragma unroll
            for (int mf = 0; mf < MF; mf++)
                ldsm_x4(af[mf], a_base + (mf * 16 * TS_H + ks * 16) * 2);
            #pragma unroll
            for (int nf = 0; nf < NF; nf++)
                ldsm_x2(bf[nf], b_base + (nf * 8 * TS_H + ks * 16) * 2);
            #pragma unroll
            for (int mf = 0; mf < MF; mf++)
                #pragma unroll
                for (int nf = 0; nf < NF; nf++)
                    mma_f16(acc[mf][nf],
                            af[mf][0], af[mf][1], af[mf][2], af[mf][3],
                            bf[nf][0], bf[nf][1]);
        }
    };

    const int NIT = K / BK;                      // 16
    stage(0, sh16);
    for (int it = 0; it < NIT; it++) {
        if (it + 1 < NIT) {
            stage((it + 1) * BK, sh16 + ((it + 1) & 1) * BUFH);
            cp_wait<1>();
        } else {
            cp_wait<0>();
        }
        __syncthreads();
        compute(sh16 + (it & 1) * BUFH);
        __syncthreads();
    }

    #pragma unroll
    for (int mf = 0; mf < MF; mf++) {
        #pragma unroll
        for (int nf = 0; nf < NF; nf++) {
            const int m0 = bm + wm * WT_M + mf * 16 + gid;
            const int n0 = bn + wn * WT_N + nf * 8 + tig * 2;
            const float bs0 = bias[n0], bs1 = bias[n0 + 1];
            if (F32OUT) {
                float* C = (float*)Cv;
                *(float2*)&C[(size_t)m0 * N + n0] =
                    make_float2(acc[mf][nf].x + bs0, acc[mf][nf].y + bs1);
                *(float2*)&C[(size_t)(m0 + 8) * N + n0] =
                    make_float2(acc[mf][nf].z + bs0, acc[mf][nf].w + bs1);
            } else {
                __half* C = (__half*)Cv;
                *(__half2*)&C[(size_t)m0 * N + n0] =
                    __floats2half2_rn(acc[mf][nf].x + bs0, acc[mf][nf].y + bs1);
                *(__half2*)&C[(size_t)(m0 + 8) * N + n0] =
                    __floats2half2_rn(acc[mf][nf].z + bs0, acc[mf][nf].w + bs1);
            }
        }
    }
}

#define QKV_SMEM ((BM * TS_H + 128 * TS_H) * 2 * 2)   // 40960 B
#define OUT_SMEM ((BM * TS_H + 64 * TS_H) * 2 * 2)    // 30720 B

// ---------------------------------------------------------------------------
// Sliding-window attention (unchanged from R14 winner).
// ---------------------------------------------------------------------------
#define TQ 64
#define TC 128
#define QS_H 72
#define KS_H 72
#define VS_H 72
#define P_H  136
#define ATTN_H (TQ * QS_H + TC * KS_H + TC * VS_H + TQ * P_H)
#define ATTN_SMEM_BYTES (ATTN_H * 2)

__global__ __launch_bounds__(256, 2) void window_attn_f16(
    const __half* __restrict__ qkv, __half* __restrict__ out)
{
    const int s0  = blockIdx.x * TQ;
    const int h   = blockIdx.y;
    const int b   = blockIdx.z;
    const int tid = threadIdx.x;

    extern __shared__ __half sh16[];
    __half* Qs = sh16;
    __half* Ks = Qs + TQ * QS_H;
    __half* Vs = Ks + TC * KS_H;
    __half* P  = Vs + TC * VS_H;

    const int w    = tid >> 5;
    const int lane = tid & 31;
    const int gid  = lane >> 2;
    const int tig  = lane & 3;
    const int wm   = w & 1;
    const int wn   = w >> 1;

    const size_t mrow = (size_t)b * SEQ;
    const int hoff = h * HD;

    {
        #pragma unroll
        for (int p = 0; p < 2; p++) {
            const int q = p * 256 + tid;
            const int r = q >> 3, ch = (q & 7) * 8;
            cp16(smem_u32(&Qs[r * QS_H + ch]),
                 &qkv[(mrow + s0 + r) * NQKV + hoff + ch], 16);
        }
        #pragma unroll
        for (int p = 0; p < 4; p++) {
            const int q = p * 256 + tid;
            const int r = q >> 3, ch = (q & 7) * 8;
            const int idx = s0 - WIN + r;
            const bool v = (idx >= 0) && (idx < SEQ);
            const int idxc = v ? idx : 0;
            cp16(smem_u32(&Ks[r * KS_H + ch]),
                 &qkv[(mrow + idxc) * NQKV + D_MODEL + hoff + ch], v ? 16 : 0);
        }
        #pragma unroll
        for (int p = 0; p < 4; p++) {
            const int q = p * 256 + tid;
            const int r = q >> 3, ch = (q & 7) * 8;
            const int idx = s0 - WIN + r;
            const bool v = (idx >= 0) && (idx < SEQ);
            const int idxc = v ? idx : 0;
            cp16(smem_u32(&Vs[r * VS_H + ch]),
                 &qkv[(mrow + idxc) * NQKV + 2 * D_MODEL + hoff + ch], v ? 16 : 0);
        }
        cp_commit();
        cp_wait<0>();
    }
    __syncthreads();

    // GEMM1: S = Q @ K^T
    {
        float4 acc[2][4];
        #pragma unroll
        for (int i = 0; i < 2; i++)
            #pragma unroll
            for (int j = 0; j < 4; j++)
                acc[i][j] = make_float4(0.f, 0.f, 0.f, 0.f);

        const unsigned a_base = smem_u32(
            &Qs[(wm * 32 + (lane & 15)) * QS_H + ((lane >> 4) * 8)]);
        const unsigned b_base = smem_u32(
            &Ks[(wn * 32 + (lane & 7)) * KS_H + (((lane >> 3) & 1) * 8)]);

        #pragma unroll
        for (int ks = 0; ks < 4; ks++) {
            unsigned af[2][4], bf[4][2];
            #pragma unroll
            for (int mf = 0; mf < 2; mf++)
                ldsm_x4(af[mf], a_base + (mf * 16 * QS_H + ks * 16) * 2);
            #pragma unroll
            for (int nf = 0; nf < 4; nf++)
                ldsm_x2(bf[nf], b_base + (nf * 8 * KS_H + ks * 16) * 2);
            #pragma unroll
            for (int mf = 0; mf < 2; mf++)
                #pragma unroll
                for (int nf = 0; nf < 4; nf++)
                    mma_f16(acc[mf][nf],
                            af[mf][0], af[mf][1], af[mf][2], af[mf][3],
                            bf[nf][0], bf[nf][1]);
        }
        #pragma unroll
        for (int mf = 0; mf < 2; mf++) {
            #pragma unroll
            for (int nf = 0; nf < 4; nf++) {
                const int m0 = wm * 32 + mf * 16 + gid;
                const int n0 = wn * 32 + nf * 8 + tig * 2;
                *(__half2*)&P[m0 * P_H + n0] =
                    __floats2half2_rn(acc[mf][nf].x, acc[mf][nf].y);
                *(__half2*)&P[(m0 + 8) * P_H + n0] =
                    __floats2half2_rn(acc[mf][nf].z, acc[mf][nf].w);
            }
        }
    }
    __syncthreads();

    // Masked softmax (fp32, scale 1/8 here)
    {
        for (int q = w; q < TQ; q += 8) {
            float vals[4];
            #pragma unroll
            for (int k = 0; k < 4; k++) {
                const int c = lane + k * 32;
                const int idx = s0 - WIN + c;
                const bool valid = (c >= q) && (c <= q + 2 * WIN) && (idx >= 0) && (idx < SEQ);
                vals[k] = valid ? __half2float(P[q * P_H + c]) * 0.125f : -1e30f;
            }
            float m = fmaxf(fmaxf(vals[0], vals[1]), fmaxf(vals[2], vals[3]));
            #pragma unroll
            for (int off = 16; off > 0; off >>= 1)
                m = fmaxf(m, __shfl_xor_sync(0xffffffffu, m, off));
            float e[4], sum = 0.f;
            #pragma unroll
            for (int k = 0; k < 4; k++) { e[k] = __expf(vals[k] - m); sum += e[k]; }
            #pragma unroll
            for (int off = 16; off > 0; off >>= 1)
                sum += __shfl_xor_sync(0xffffffffu, sum, off);
            const float inv = 1.0f / sum;
            #pragma unroll
            for (int k = 0; k < 4; k++)
                P[q * P_H + lane + k * 32] = __float2half_rn(e[k] * inv);
        }
    }
    __syncthreads();

    // GEMM2: O = P @ V (V via ldmatrix.trans)
    {
        float4 acc[2][2];
        #pragma unroll
        for (int i = 0; i < 2; i++)
            #pragma unroll
            for (int j = 0; j < 2; j++)
                acc[i][j] = make_float4(0.f, 0.f, 0.f, 0.f);

        const unsigned p_base = smem_u32(
            &P[(wm * 32 + (lane & 15)) * P_H + ((lane >> 4) * 8)]);
        const int l2 = lane & 15;

        #pragma unroll
        for (int ks = 0; ks < 8; ks++) {
            unsigned af[2][4], bf[2][2];
            #pragma unroll
            for (int mf = 0; mf < 2; mf++)
                ldsm_x4(af[mf], p_base + (mf * 16 * P_H + ks * 16) * 2);
            #pragma unroll
            for (int nf = 0; nf < 2; nf++) {
                const int nb = wn * 16 + nf * 8;
                ldsm_x2_trans(bf[nf], smem_u32(&Vs[(ks * 16 + l2) * VS_H + nb]));
            }
            #pragma unroll
            for (int mf = 0; mf < 2; mf++)
                #pragma unroll
                for (int nf = 0; nf < 2; nf++)
                    mma_f16(acc[mf][nf],
                            af[mf][0], af[mf][1], af[mf][2], af[mf][3],
                            bf[nf][0], bf[nf][1]);
        }
        #pragma unroll
        for (int mf = 0; mf < 2; mf++) {
            #pragma unroll
            for (int nf = 0; nf < 2; nf++) {
                const int m0 = wm * 32 + mf * 16 + gid;
                const int n0 = wn * 16 + nf * 8 + tig * 2;
                size_t o0 = ((size_t)b * SEQ + s0 + m0) * D_MODEL + hoff + n0;
                *(__half2*)&out[o0] = __floats2half2_rn(acc[mf][nf].x, acc[mf][nf].y);
                size_t o1 = ((size_t)b * SEQ + s0 + m0 + 8) * D_MODEL + hoff + n0;
                *(__half2*)&out[o1] = __floats2half2_rn(acc[mf][nf].z, acc[mf][nf].w);
            }
        }
    }
}

// ---------------------------------------------------------------------------
extern "C" void kernel_launch(void* const* d_in, const int* in_sizes, int n_in,
                              void* d_out, int out_size)
{
    const float* x     = (const float*)d_in[0];
    const float* w_qkv = (const float*)d_in[1];
    const float* b_qkv = (const float*)d_in[2];
    const float* w_out = (const float*)d_in[3];
    const float* b_out = (const float*)d_in[4];
    float* out = (float*)d_out;

    __half *xh, *qkv, *attn, *wqt, *wot;
    cudaGetSymbolAddress((void**)&xh,   g_xh);
    cudaGetSymbolAddress((void**)&qkv,  g_qkv);
    cudaGetSymbolAddress((void**)&attn, g_attn);
    cudaGetSymbolAddress((void**)&wqt,  g_wqkv_t);
    cudaGetSymbolAddress((void**)&wot,  g_wout_t);

    cudaFuncSetAttribute((const void*)gemm_h<128, false>,
                         cudaFuncAttributeMaxDynamicSharedMemorySize, QKV_SMEM);
    cudaFuncSetAttribute((const void*)gemm_h<64, true>,
                         cudaFuncAttributeMaxDynamicSharedMemorySize, OUT_SMEM);
    cudaFuncSetAttribute(window_attn_f16,
                         cudaFuncAttributeMaxDynamicSharedMemorySize, ATTN_SMEM_BYTES);

    // 0) Fused prep: weight transposes + x conversion (one launch)
    prep<<<2048, 256>>>(w_qkv, w_out, x, wqt, wot, xh);

    // 1) QKV projection (all-half, cp.async pipeline)
    {
        dim3 grid(NQKV / 128, MTOT / BM);         // 12 x 32
        gemm_h<128, false><<<grid, 256, QKV_SMEM>>>(
            xh, wqt, b_qkv, qkv, MTOT, NQKV, D_MODEL);
    }
    // 2) Windowed attention
    {
        dim3 grid(SEQ / TQ, NHEAD, BATCH);        // 512 CTAs
        window_attn_f16<<<grid, 256, ATTN_SMEM_BYTES>>>(qkv, attn);
    }
    // 3) Output projection (half A, f32 out)
    {
        dim3 grid(D_MODEL / 64, MTOT / BM);       // 256 CTAs
        gemm_h<64, true><<<grid, 256, OUT_SMEM>>>(
            attn, wot, b_out, out, MTOT, D_MODEL, D_MODEL);
    }
}

// round 17
// speedup vs baseline: 2.3130x; 1.0916x over previous
#include <cuda_runtime.h>
#include <cuda_fp16.h>
#include <cstdint>
#include <math.h>

#define D_MODEL 512
#define NHEAD   8
#define HD      64
#define WIN     32
#define BATCH   2
#define SEQ     2048
#define MTOT    (BATCH * SEQ)          // 4096
#define NQKV    (3 * D_MODEL)          // 1536

// Scratch (no cudaMalloc allowed)
__device__ __half g_xh[MTOT * D_MODEL];          // x as half
__device__ __half g_qkv[MTOT * NQKV];            // [m][1536] half
__device__ __half g_wqkv_t[NQKV * D_MODEL];      // w_qkv^T [n][k] half
__device__ __half g_wout_t[D_MODEL * D_MODEL];   // w_out^T [n][k] half
__device__ __half g_attn[MTOT * D_MODEL];        // [m][512] half

__device__ __forceinline__ unsigned smem_u32(const void* p) {
    return (unsigned)__cvta_generic_to_shared(p);
}
__device__ __forceinline__ void ldsm_x4(unsigned int* r, unsigned addr) {
    asm volatile("ldmatrix.sync.aligned.m8n8.x4.shared.b16 {%0,%1,%2,%3}, [%4];"
        : "=r"(r[0]), "=r"(r[1]), "=r"(r[2]), "=r"(r[3]) : "r"(addr));
}
__device__ __forceinline__ void ldsm_x2(unsigned int* r, unsigned addr) {
    asm volatile("ldmatrix.sync.aligned.m8n8.x2.shared.b16 {%0,%1}, [%2];"
        : "=r"(r[0]), "=r"(r[1]) : "r"(addr));
}
__device__ __forceinline__ void ldsm_x2_trans(unsigned int* r, unsigned addr) {
    asm volatile("ldmatrix.sync.aligned.m8n8.x2.trans.shared.b16 {%0,%1}, [%2];"
        : "=r"(r[0]), "=r"(r[1]) : "r"(addr));
}
__device__ __forceinline__ void mma_f16(float4& d,
    unsigned a0, unsigned a1, unsigned a2, unsigned a3,
    unsigned b0, unsigned b1)
{
    asm volatile(
        "mma.sync.aligned.m16n8k16.row.col.f32.f16.f16.f32 "
        "{%0,%1,%2,%3}, {%4,%5,%6,%7}, {%8,%9}, {%0,%1,%2,%3};\n"
        : "+f"(d.x), "+f"(d.y), "+f"(d.z), "+f"(d.w)
        : "r"(a0), "r"(a1), "r"(a2), "r"(a3), "r"(b0), "r"(b1));
}
__device__ __forceinline__ void cp16(unsigned dst, const void* src, int src_sz) {
    asm volatile("cp.async.cg.shared.global [%0], [%1], 16, %2;"
        :: "r"(dst), "l"(src), "r"(src_sz) : "memory");
}
__device__ __forceinline__ void cp_commit() {
    asm volatile("cp.async.commit_group;" ::: "memory");
}
template<int N>
__device__ __forceinline__ void cp_wait() {
    asm volatile("cp.async.wait_group %0;" :: "n"(N) : "memory");
}

// ---------------------------------------------------------------------------
// Fused prep: [0,768) w_qkv^T tiles, [768,1024) w_out^T tiles,
// [1024,2048) x f32->half conversion.
// ---------------------------------------------------------------------------
__global__ __launch_bounds__(256) void prep(
    const float* __restrict__ w_qkv, const float* __restrict__ w_out,
    const float* __restrict__ x,
    __half* __restrict__ wqt, __half* __restrict__ wot, __half* __restrict__ xh)
{
    const int bid = blockIdx.x;
    if (bid < 1024) {
        const float* w; __half* wt; int K, N, bx, by;
        if (bid < 768) { w = w_qkv; wt = wqt; K = D_MODEL; N = NQKV;
                         bx = (bid % 48) * 32; by = (bid / 48) * 32; }
        else { int b2 = bid - 768; w = w_out; wt = wot; K = D_MODEL; N = D_MODEL;
               bx = (b2 % 16) * 32; by = (b2 / 16) * 32; }
        __shared__ float t[32][33];
        const int xx = threadIdx.x & 31;
        const int y0 = threadIdx.x >> 5;
        #pragma unroll
        for (int j = 0; j < 32; j += 8)
            t[y0 + j][xx] = w[(size_t)(by + y0 + j) * N + bx + xx];
        __syncthreads();
        #pragma unroll
        for (int j = 0; j < 32; j += 8)
            wt[(size_t)(bx + y0 + j) * K + by + xx] = __float2half_rn(t[xx][y0 + j]);
    } else {
        const size_t base = (size_t)(bid - 1024) * 2048 + threadIdx.x * 8;
        float4 f0 = *(const float4*)&x[base];
        float4 f1 = *(const float4*)&x[base + 4];
        __half2 h0 = __floats2half2_rn(f0.x, f0.y);
        __half2 h1 = __floats2half2_rn(f0.z, f0.w);
        __half2 h2 = __floats2half2_rn(f1.x, f1.y);
        __half2 h3 = __floats2half2_rn(f1.z, f1.w);
        uint4 v;
        v.x = *(unsigned*)&h0; v.y = *(unsigned*)&h1;
        v.z = *(unsigned*)&h2; v.w = *(unsigned*)&h3;
        *(uint4*)&xh[base] = v;
    }
}

// ---------------------------------------------------------------------------
// All-half fp16 GEMM, 3-buffer cp.async ring (depth 2), ONE sync per iter.
// C[M,N] = A[m][k] @ Bt[n][k]^T + bias.  F32OUT selects output dtype.
// BM=128, BK=32, 256 threads = 8 warps.
// ---------------------------------------------------------------------------
#define BM 128
#define BK 32
#define TS_H 40

template<int BN_, bool F32OUT>
__global__ __launch_bounds__(256, 2) void gemm_h(
    const __half* __restrict__ A, const __half* __restrict__ Bt,
    const float* __restrict__ bias, void* __restrict__ Cv,
    int M, int N, int K)
{
    constexpr int WM_WARPS = (BN_ == 128) ? 2 : 4;
    constexpr int WT_M = BM / WM_WARPS;
    constexpr int WT_N = BN_ / (8 / WM_WARPS);
    constexpr int MF = WT_M / 16;
    constexpr int NF = WT_N / 8;
    constexpr int BUFH = BM * TS_H + BN_ * TS_H;
    constexpr int BSEG = BN_ / 64;

    extern __shared__ __half sh16[];

    const int tid  = threadIdx.x;
    const int bm   = blockIdx.y * BM;
    const int bn   = blockIdx.x * BN_;
    const int w    = tid >> 5;
    const int wm   = w % WM_WARPS;
    const int wn   = w / WM_WARPS;
    const int lane = tid & 31;
    const int gid  = lane >> 2;
    const int tig  = lane & 3;

    float4 acc[MF][NF];
    #pragma unroll
    for (int i = 0; i < MF; i++)
        #pragma unroll
        for (int j = 0; j < NF; j++)
            acc[i][j] = make_float4(0.f, 0.f, 0.f, 0.f);

    auto stage = [&](int k0, __half* base) {
        __half* As = base;
        __half* Bs = base + BM * TS_H;
        #pragma unroll
        for (int p = 0; p < 2; p++) {
            const int idx = p * 256 + tid;
            const int r = idx >> 2, c8 = (idx & 3) * 8;
            cp16(smem_u32(&As[r * TS_H + c8]),
                 &A[(size_t)(bm + r) * K + k0 + c8], 16);
        }
        #pragma unroll
        for (int p = 0; p < BSEG; p++) {
            const int idx = p * 256 + tid;
            const int r = idx >> 2, c8 = (idx & 3) * 8;
            cp16(smem_u32(&Bs[r * TS_H + c8]),
                 &Bt[(size_t)(bn + r) * K + k0 + c8], 16);
        }
        cp_commit();
    };
    auto compute = [&](const __half* base) {
        const __half* As = base;
        const __half* Bs = base + BM * TS_H;
        const unsigned a_base = smem_u32(
            &As[(wm * WT_M + (lane & 15)) * TS_H + ((lane >> 4) * 8)]);
        const unsigned b_base = smem_u32(
            &Bs[(wn * WT_N + (lane & 7)) * TS_H + (((lane >> 3) & 1) * 8)]);
        #pragma unroll
        for (int ks = 0; ks < 2; ks++) {
            unsigned af[MF][4], bf[NF][2];
            #pragma unroll
            for (int mf = 0; mf < MF; mf++)
                ldsm_x4(af[mf], a_base + (mf * 16 * TS_H + ks * 16) * 2);
            #pragma unroll
            for (int nf = 0; nf < NF; nf++)
                ldsm_x2(bf[nf], b_base + (nf * 8 * TS_H + ks * 16) * 2);
            #pragma unroll
            for (int mf = 0; mf < MF; mf++)
                #pragma unroll
                for (int nf = 0; nf < NF; nf++)
                    mma_f16(acc[mf][nf],
                            af[mf][0], af[mf][1], af[mf][2], af[mf][3],
                            bf[nf][0], bf[nf][1]);
        }
    };

    const int NIT = K / BK;                      // 16
    stage(0, sh16);
    stage(BK, sh16 + BUFH);
    int bufc = 0;                                // compute buffer index (mod 3)
    for (int it = 0; it < NIT; it++) {
        if (it + 1 < NIT) cp_wait<1>(); else cp_wait<0>();
        __syncthreads();
        compute(sh16 + bufc * BUFH);
        if (it + 2 < NIT) {
            int bufs = bufc + 2; if (bufs >= 3) bufs -= 3;
            stage((it + 2) * BK, sh16 + bufs * BUFH);
        }
        if (++bufc == 3) bufc = 0;
    }

    #pragma unroll
    for (int mf = 0; mf < MF; mf++) {
        #pragma unroll
        for (int nf = 0; nf < NF; nf++) {
            const int m0 = bm + wm * WT_M + mf * 16 + gid;
            const int n0 = bn + wn * WT_N + nf * 8 + tig * 2;
            const float bs0 = bias[n0], bs1 = bias[n0 + 1];
            if (F32OUT) {
                float* C = (float*)Cv;
                *(float2*)&C[(size_t)m0 * N + n0] =
                    make_float2(acc[mf][nf].x + bs0, acc[mf][nf].y + bs1);
                *(float2*)&C[(size_t)(m0 + 8) * N + n0] =
                    make_float2(acc[mf][nf].z + bs0, acc[mf][nf].w + bs1);
            } else {
                __half* C = (__half*)Cv;
                *(__half2*)&C[(size_t)m0 * N + n0] =
                    __floats2half2_rn(acc[mf][nf].x + bs0, acc[mf][nf].y + bs1);
                *(__half2*)&C[(size_t)(m0 + 8) * N + n0] =
                    __floats2half2_rn(acc[mf][nf].z + bs0, acc[mf][nf].w + bs1);
            }
        }
    }
}

#define QKV_SMEM ((BM * TS_H + 128 * TS_H) * 3 * 2)   // 61440 B
#define OUT_SMEM ((BM * TS_H + 64 * TS_H) * 3 * 2)    // 46080 B

// ---------------------------------------------------------------------------
// Sliding-window attention (unchanged from R14/R15 winner).
// ---------------------------------------------------------------------------
#define TQ 64
#define TC 128
#define QS_H 72
#define KS_H 72
#define VS_H 72
#define P_H  136
#define ATTN_H (TQ * QS_H + TC * KS_H + TC * VS_H + TQ * P_H)
#define ATTN_SMEM_BYTES (ATTN_H * 2)

__global__ __launch_bounds__(256, 2) void window_attn_f16(
    const __half* __restrict__ qkv, __half* __restrict__ out)
{
    const int s0  = blockIdx.x * TQ;
    const int h   = blockIdx.y;
    const int b   = blockIdx.z;
    const int tid = threadIdx.x;

    extern __shared__ __half sh16[];
    __half* Qs = sh16;
    __half* Ks = Qs + TQ * QS_H;
    __half* Vs = Ks + TC * KS_H;
    __half* P  = Vs + TC * VS_H;

    const int w    = tid >> 5;
    const int lane = tid & 31;
    const int gid  = lane >> 2;
    const int tig  = lane & 3;
    const int wm   = w & 1;
    const int wn   = w >> 1;

    const size_t mrow = (size_t)b * SEQ;
    const int hoff = h * HD;

    {
        #pragma unroll
        for (int p = 0; p < 2; p++) {
            const int q = p * 256 + tid;
            const int r = q >> 3, ch = (q & 7) * 8;
            cp16(smem_u32(&Qs[r * QS_H + ch]),
                 &qkv[(mrow + s0 + r) * NQKV + hoff + ch], 16);
        }
        #pragma unroll
        for (int p = 0; p < 4; p++) {
            const int q = p * 256 + tid;
            const int r = q >> 3, ch = (q & 7) * 8;
            const int idx = s0 - WIN + r;
            const bool v = (idx >= 0) && (idx < SEQ);
            const int idxc = v ? idx : 0;
            cp16(smem_u32(&Ks[r * KS_H + ch]),
                 &qkv[(mrow + idxc) * NQKV + D_MODEL + hoff + ch], v ? 16 : 0);
        }
        #pragma unroll
        for (int p = 0; p < 4; p++) {
            const int q = p * 256 + tid;
            const int r = q >> 3, ch = (q & 7) * 8;
            const int idx = s0 - WIN + r;
            const bool v = (idx >= 0) && (idx < SEQ);
            const int idxc = v ? idx : 0;
            cp16(smem_u32(&Vs[r * VS_H + ch]),
                 &qkv[(mrow + idxc) * NQKV + 2 * D_MODEL + hoff + ch], v ? 16 : 0);
        }
        cp_commit();
        cp_wait<0>();
    }
    __syncthreads();

    // GEMM1: S = Q @ K^T
    {
        float4 acc[2][4];
        #pragma unroll
        for (int i = 0; i < 2; i++)
            #pragma unroll
            for (int j = 0; j < 4; j++)
                acc[i][j] = make_float4(0.f, 0.f, 0.f, 0.f);

        const unsigned a_base = smem_u32(
            &Qs[(wm * 32 + (lane & 15)) * QS_H + ((lane >> 4) * 8)]);
        const unsigned b_base = smem_u32(
            &Ks[(wn * 32 + (lane & 7)) * KS_H + (((lane >> 3) & 1) * 8)]);

        #pragma unroll
        for (int ks = 0; ks < 4; ks++) {
            unsigned af[2][4], bf[4][2];
            #pragma unroll
            for (int mf = 0; mf < 2; mf++)
                ldsm_x4(af[mf], a_base + (mf * 16 * QS_H + ks * 16) * 2);
            #pragma unroll
            for (int nf = 0; nf < 4; nf++)
                ldsm_x2(bf[nf], b_base + (nf * 8 * KS_H + ks * 16) * 2);
            #pragma unroll
            for (int mf = 0; mf < 2; mf++)
                #pragma unroll
                for (int nf = 0; nf < 4; nf++)
                    mma_f16(acc[mf][nf],
                            af[mf][0], af[mf][1], af[mf][2], af[mf][3],
                            bf[nf][0], bf[nf][1]);
        }
        #pragma unroll
        for (int mf = 0; mf < 2; mf++) {
            #pragma unroll
            for (int nf = 0; nf < 4; nf++) {
                const int m0 = wm * 32 + mf * 16 + gid;
                const int n0 = wn * 32 + nf * 8 + tig * 2;
                *(__half2*)&P[m0 * P_H + n0] =
                    __floats2half2_rn(acc[mf][nf].x, acc[mf][nf].y);
                *(__half2*)&P[(m0 + 8) * P_H + n0] =
                    __floats2half2_rn(acc[mf][nf].z, acc[mf][nf].w);
            }
        }
    }
    __syncthreads();

    // Masked softmax (fp32, scale 1/8 here)
    {
        for (int q = w; q < TQ; q += 8) {
            float vals[4];
            #pragma unroll
            for (int k = 0; k < 4; k++) {
                const int c = lane + k * 32;
                const int idx = s0 - WIN + c;
                const bool valid = (c >= q) && (c <= q + 2 * WIN) && (idx >= 0) && (idx < SEQ);
                vals[k] = valid ? __half2float(P[q * P_H + c]) * 0.125f : -1e30f;
            }
            float m = fmaxf(fmaxf(vals[0], vals[1]), fmaxf(vals[2], vals[3]));
            #pragma unroll
            for (int off = 16; off > 0; off >>= 1)
                m = fmaxf(m, __shfl_xor_sync(0xffffffffu, m, off));
            float e[4], sum = 0.f;
            #pragma unroll
            for (int k = 0; k < 4; k++) { e[k] = __expf(vals[k] - m); sum += e[k]; }
            #pragma unroll
            for (int off = 16; off > 0; off >>= 1)
                sum += __shfl_xor_sync(0xffffffffu, sum, off);
            const float inv = 1.0f / sum;
            #pragma unroll
            for (int k = 0; k < 4; k++)
                P[q * P_H + lane + k * 32] = __float2half_rn(e[k] * inv);
        }
    }
    __syncthreads();

    // GEMM2: O = P @ V (V via ldmatrix.trans)
    {
        float4 acc[2][2];
        #pragma unroll
        for (int i = 0; i < 2; i++)
            #pragma unroll
            for (int j = 0; j < 2; j++)
                acc[i][j] = make_float4(0.f, 0.f, 0.f, 0.f);

        const unsigned p_base = smem_u32(
            &P[(wm * 32 + (lane & 15)) * P_H + ((lane >> 4) * 8)]);
        const int l2 = lane & 15;

        #pragma unroll
        for (int ks = 0; ks < 8; ks++) {
            unsigned af[2][4], bf[2][2];
            #pragma unroll
            for (int mf = 0; mf < 2; mf++)
                ldsm_x4(af[mf], p_base + (mf * 16 * P_H + ks * 16) * 2);
            #pragma unroll
            for (int nf = 0; nf < 2; nf++) {
                const int nb = wn * 16 + nf * 8;
                ldsm_x2_trans(bf[nf], smem_u32(&Vs[(ks * 16 + l2) * VS_H + nb]));
            }
            #pragma unroll
            for (int mf = 0; mf < 2; mf++)
                #pragma unroll
                for (int nf = 0; nf < 2; nf++)
                    mma_f16(acc[mf][nf],
                            af[mf][0], af[mf][1], af[mf][2], af[mf][3],
                            bf[nf][0], bf[nf][1]);
        }
        #pragma unroll
        for (int mf = 0; mf < 2; mf++) {
            #pragma unroll
            for (int nf = 0; nf < 2; nf++) {
                const int m0 = wm * 32 + mf * 16 + gid;
                const int n0 = wn * 16 + nf * 8 + tig * 2;
                size_t o0 = ((size_t)b * SEQ + s0 + m0) * D_MODEL + hoff + n0;
                *(__half2*)&out[o0] = __floats2half2_rn(acc[mf][nf].x, acc[mf][nf].y);
                size_t o1 = ((size_t)b * SEQ + s0 + m0 + 8) * D_MODEL + hoff + n0;
                *(__half2*)&out[o1] = __floats2half2_rn(acc[mf][nf].z, acc[mf][nf].w);
            }
        }
    }
}

// ---------------------------------------------------------------------------
extern "C" void kernel_launch(void* const* d_in, const int* in_sizes, int n_in,
                              void* d_out, int out_size)
{
    const float* x     = (const float*)d_in[0];
    const float* w_qkv = (const float*)d_in[1];
    const float* b_qkv = (const float*)d_in[2];
    const float* w_out = (const float*)d_in[3];
    const float* b_out = (const float*)d_in[4];
    float* out = (float*)d_out;

    __half *xh, *qkv, *attn, *wqt, *wot;
    cudaGetSymbolAddress((void**)&xh,   g_xh);
    cudaGetSymbolAddress((void**)&qkv,  g_qkv);
    cudaGetSymbolAddress((void**)&attn, g_attn);
    cudaGetSymbolAddress((void**)&wqt,  g_wqkv_t);
    cudaGetSymbolAddress((void**)&wot,  g_wout_t);

    cudaFuncSetAttribute((const void*)gemm_h<128, false>,
                         cudaFuncAttributeMaxDynamicSharedMemorySize, QKV_SMEM);
    cudaFuncSetAttribute((const void*)gemm_h<64, true>,
                         cudaFuncAttributeMaxDynamicSharedMemorySize, OUT_SMEM);
    cudaFuncSetAttribute(window_attn_f16,
                         cudaFuncAttributeMaxDynamicSharedMemorySize, ATTN_SMEM_BYTES);

    // 0) Fused prep: weight transposes + x conversion (one launch)
    prep<<<2048, 256>>>(w_qkv, w_out, x, wqt, wot, xh);

    // 1) QKV projection (all-half, 3-buffer cp.async ring)
    {
        dim3 grid(NQKV / 128, MTOT / BM);         // 12 x 32
        gemm_h<128, false><<<grid, 256, QKV_SMEM>>>(
            xh, wqt, b_qkv, qkv, MTOT, NQKV, D_MODEL);
    }
    // 2) Windowed attention
    {
        dim3 grid(SEQ / TQ, NHEAD, BATCH);        // 512 CTAs
        window_attn_f16<<<grid, 256, ATTN_SMEM_BYTES>>>(qkv, attn);
    }
    // 3) Output projection (half A, f32 out)
    {
        dim3 grid(D_MODEL / 64, MTOT / BM);       // 256 CTAs
        gemm_h<64, true><<<grid, 256, OUT_SMEM>>>(
            attn, wot, b_out, out, MTOT, D_MODEL, D_MODEL);
    }
}